// round 4
// baseline (speedup 1.0000x reference)
#include <cuda_runtime.h>
#include <cstdint>

#define Bsz 2
#define Ssz 1024
#define Dm  1024
#define Hh  16
#define DKk 64
#define Ff  4096
#define Vv  32000
#define Ll  8
#define TOK (Bsz*Ssz)

// ---------------- scratch (static device globals: allocation-free) ----------
__device__ float g_x [TOK*Dm];
__device__ float g_h [TOK*Dm];
__device__ float g_q [TOK*Dm];
__device__ float g_k [TOK*Dm];
__device__ float g_v [TOK*Dm];
__device__ float g_o [TOK*Dm];
__device__ float g_ff[TOK*Ff];
__device__ float g_sc[(size_t)Bsz*Hh*Ssz*Ssz];   // 128 MB

// ---------------- embedding: x = tok_emb[ids] + pos_emb[:S] -----------------
__global__ __launch_bounds__(256) void embed_k(
    const int* __restrict__ ids, const float* __restrict__ tok,
    const float* __restrict__ pos, float* __restrict__ x)
{
    const int row = blockIdx.x;            // 0..TOK-1
    const int s   = row & (Ssz - 1);
    const int id  = ids[row];
    const int t   = threadIdx.x;           // 256 threads, 4 floats each
    float4 tv = *(const float4*)(tok + (size_t)id * Dm + t * 4);
    float4 pv = *(const float4*)(pos + (size_t)s  * Dm + t * 4);
    float4 o; o.x = tv.x + pv.x; o.y = tv.y + pv.y; o.z = tv.z + pv.z; o.w = tv.w + pv.w;
    *(float4*)(x + (size_t)row * Dm + t * 4) = o;
}

// ---------------- layernorm (one block per row, D=1024) ---------------------
__global__ __launch_bounds__(256) void layernorm_k(
    const float* __restrict__ x, const float* __restrict__ g,
    const float* __restrict__ be, float* __restrict__ out)
{
    const int row = blockIdx.x;
    const int t   = threadIdx.x;
    const float* xr = x + (size_t)row * Dm;
    float4 v = *(const float4*)(xr + t * 4);
    float s  = v.x + v.y + v.z + v.w;
    float ss = v.x*v.x + v.y*v.y + v.z*v.z + v.w*v.w;
    #pragma unroll
    for (int off = 16; off; off >>= 1) {
        s  += __shfl_xor_sync(0xffffffffu, s,  off);
        ss += __shfl_xor_sync(0xffffffffu, ss, off);
    }
    __shared__ float rs[8], rss[8];
    const int warp = t >> 5, lane = t & 31;
    if (lane == 0) { rs[warp] = s; rss[warp] = ss; }
    __syncthreads();
    s = 0.f; ss = 0.f;
    #pragma unroll
    for (int i = 0; i < 8; i++) { s += rs[i]; ss += rss[i]; }
    const float mean = s  * (1.0f / Dm);
    const float var  = ss * (1.0f / Dm) - mean * mean;
    const float rstd = rsqrtf(var + 1e-5f);
    float4 gv = *(const float4*)(g  + t * 4);
    float4 bv = *(const float4*)(be + t * 4);
    float4 o;
    o.x = (v.x - mean) * rstd * gv.x + bv.x;
    o.y = (v.y - mean) * rstd * gv.y + bv.y;
    o.z = (v.z - mean) * rstd * gv.z + bv.z;
    o.w = (v.w - mean) * rstd * gv.w + bv.w;
    *(float4*)(out + (size_t)row * Dm + t * 4) = o;
}

// ---------------- generic tiled SGEMM (NN): C = A@B (+bias)(+res)(relu) -----
// A [M,K] row-major lda, B [K,N] row-major ldb, C [M,N] row-major ldc.
// All dims exact multiples of the tile sizes (true for this problem).
#define F_BIAS 1
#define F_RES  2
#define F_RELU 4

template<int BM, int BN, int BK, int TM, int TN, int FLAGS>
__global__ __launch_bounds__(256) void sgemm_k(
    const float* __restrict__ A, int lda,
    const float* __restrict__ B, int ldb,
    const float* __restrict__ bias,
    const float* __restrict__ Res,
    float* __restrict__ C, int ldc, int K)
{
    constexpr int NT = (BM / TM) * (BN / TN);
    static_assert(NT == 256, "expect 256 threads");
    __shared__ float As[BK][BM];
    __shared__ float Bs[BK][BN];
    const int tid = threadIdx.x;
    const int tx  = tid % (BN / TN);
    const int ty  = tid / (BN / TN);
    const int bm = blockIdx.y, bn = blockIdx.x;
    const float* Ab = A + (size_t)bm * BM * lda;
    const float* Bb = B + (size_t)bn * BN;

    float acc[TM][TN];
    #pragma unroll
    for (int i = 0; i < TM; i++)
        #pragma unroll
        for (int j = 0; j < TN; j++) acc[i][j] = 0.f;

    for (int k0 = 0; k0 < K; k0 += BK) {
        #pragma unroll
        for (int i = tid * 4; i < BM * BK; i += NT * 4) {
            const int r = i / BK, c = i % BK;
            float4 v4 = *(const float4*)(Ab + (size_t)r * lda + (k0 + c));
            As[c + 0][r] = v4.x; As[c + 1][r] = v4.y;
            As[c + 2][r] = v4.z; As[c + 3][r] = v4.w;
        }
        #pragma unroll
        for (int i = tid * 4; i < BK * BN; i += NT * 4) {
            const int r = i / BN, c = i % BN;
            *(float4*)&Bs[r][c] = *(const float4*)(Bb + (size_t)(k0 + r) * ldb + c);
        }
        __syncthreads();
        #pragma unroll
        for (int k = 0; k < BK; k++) {
            float a[TM], bb[TN];
            #pragma unroll
            for (int i = 0; i < TM; i += 4) *(float4*)&a[i]  = *(const float4*)&As[k][ty * TM + i];
            #pragma unroll
            for (int j = 0; j < TN; j += 4) *(float4*)&bb[j] = *(const float4*)&Bs[k][tx * TN + j];
            #pragma unroll
            for (int i = 0; i < TM; i++)
                #pragma unroll
                for (int j = 0; j < TN; j++) acc[i][j] = fmaf(a[i], bb[j], acc[i][j]);
        }
        __syncthreads();
    }
    const int row0 = bm * BM + ty * TM;
    const int col0 = bn * BN + tx * TN;
    #pragma unroll
    for (int i = 0; i < TM; i++) {
        const int row = row0 + i;
        #pragma unroll
        for (int j = 0; j < TN; j += 4) {
            float4 v;
            v.x = acc[i][j]; v.y = acc[i][j+1]; v.z = acc[i][j+2]; v.w = acc[i][j+3];
            if (FLAGS & F_BIAS) {
                float4 b4 = *(const float4*)(bias + col0 + j);
                v.x += b4.x; v.y += b4.y; v.z += b4.z; v.w += b4.w;
            }
            if (FLAGS & F_RES) {
                float4 r4 = *(const float4*)(Res + (size_t)row * ldc + col0 + j);
                v.x += r4.x; v.y += r4.y; v.z += r4.z; v.w += r4.w;
            }
            if (FLAGS & F_RELU) {
                v.x = fmaxf(v.x, 0.f); v.y = fmaxf(v.y, 0.f);
                v.z = fmaxf(v.z, 0.f); v.w = fmaxf(v.w, 0.f);
            }
            *(float4*)(C + (size_t)row * ldc + col0 + j) = v;
        }
    }
}

// ---------------- attention scores: S = scale * Q @ K^T (causal blocks) -----
// per (b,h): Q,K are [S, DKk] with row stride Dm. 128x128 tiles, skip bn>bm.
__global__ __launch_bounds__(256) void attn_scores_k(
    const float* __restrict__ Q, const float* __restrict__ Kmat, float* __restrict__ Sc)
{
    const int bm = blockIdx.y, bn = blockIdx.x;
    if (bn > bm) return;                       // fully masked block
    const int bh = blockIdx.z;
    const int b = bh >> 4, h = bh & 15;
    const float* Qb = Q    + (size_t)b * Ssz * Dm + h * DKk + (size_t)bm * 128 * Dm;
    const float* Kb = Kmat + (size_t)b * Ssz * Dm + h * DKk + (size_t)bn * 128 * Dm;
    float* Cb = Sc + (size_t)bh * Ssz * Ssz;

    __shared__ float As[8][128], Bs[8][128];
    const int tid = threadIdx.x;
    const int tx = tid & 15, ty = tid >> 4;
    const int lrow = tid >> 1, lcol = (tid & 1) * 4;

    float acc[8][8];
    #pragma unroll
    for (int i = 0; i < 8; i++)
        #pragma unroll
        for (int j = 0; j < 8; j++) acc[i][j] = 0.f;

    #pragma unroll
    for (int k0 = 0; k0 < DKk; k0 += 8) {
        float4 a4 = *(const float4*)(Qb + (size_t)lrow * Dm + k0 + lcol);
        float4 b4 = *(const float4*)(Kb + (size_t)lrow * Dm + k0 + lcol);
        As[lcol+0][lrow] = a4.x; As[lcol+1][lrow] = a4.y;
        As[lcol+2][lrow] = a4.z; As[lcol+3][lrow] = a4.w;
        Bs[lcol+0][lrow] = b4.x; Bs[lcol+1][lrow] = b4.y;
        Bs[lcol+2][lrow] = b4.z; Bs[lcol+3][lrow] = b4.w;
        __syncthreads();
        #pragma unroll
        for (int k = 0; k < 8; k++) {
            float a[8], bb[8];
            #pragma unroll
            for (int i = 0; i < 8; i += 4) *(float4*)&a[i]  = *(const float4*)&As[k][ty*8 + i];
            #pragma unroll
            for (int j = 0; j < 8; j += 4) *(float4*)&bb[j] = *(const float4*)&Bs[k][tx*8 + j];
            #pragma unroll
            for (int i = 0; i < 8; i++)
                #pragma unroll
                for (int j = 0; j < 8; j++) acc[i][j] = fmaf(a[i], bb[j], acc[i][j]);
        }
        __syncthreads();
    }
    const float scale = 0.125f;                // 1/sqrt(64)
    #pragma unroll
    for (int i = 0; i < 8; i++) {
        const int q = bm * 128 + ty * 8 + i;
        #pragma unroll
        for (int j = 0; j < 8; j += 4) {
            float4 v;
            v.x = acc[i][j]   * scale; v.y = acc[i][j+1] * scale;
            v.z = acc[i][j+2] * scale; v.w = acc[i][j+3] * scale;
            *(float4*)(Cb + (size_t)q * Ssz + bn * 128 + tx * 8 + j) = v;
        }
    }
}

// ---------------- causal softmax: warp per row -------------------------------
// writes normalized probs for k<=q, zeros for q<k<kend (64-aligned block end)
__global__ __launch_bounds__(256) void softmax_k(float* __restrict__ Sc)
{
    const int warp = threadIdx.x >> 5, lane = threadIdx.x & 31;
    const int row = blockIdx.x * 8 + warp;          // 0..B*H*S-1
    const int bh = row >> 10, q = row & 1023;
    float* r = Sc + (size_t)bh * Ssz * Ssz + (size_t)q * Ssz;
    const int n = q + 1;
    float vals[32];
    float m = -3.0e38f;
    #pragma unroll
    for (int i = 0; i < 32; i++) {
        const int k = lane + i * 32;
        float v = (k < n) ? r[k] : -3.0e38f;
        vals[i] = v; m = fmaxf(m, v);
    }
    #pragma unroll
    for (int off = 16; off; off >>= 1) m = fmaxf(m, __shfl_xor_sync(0xffffffffu, m, off));
    float s = 0.f;
    #pragma unroll
    for (int i = 0; i < 32; i++) { float e = __expf(vals[i] - m); vals[i] = e; s += e; }
    #pragma unroll
    for (int off = 16; off; off >>= 1) s += __shfl_xor_sync(0xffffffffu, s, off);
    const float inv = 1.0f / s;
    const int kend = ((q >> 6) + 1) << 6;
    #pragma unroll
    for (int i = 0; i < 32; i++) {
        const int k = lane + i * 32;
        if (k < kend) r[k] = (k < n) ? vals[i] * inv : 0.f;
    }
}

// ---------------- O = P @ V per (b,h): [S,S]@[S,DKk], K-loop truncated -------
__global__ __launch_bounds__(256) void attn_av_k(
    const float* __restrict__ P, const float* __restrict__ Vm, float* __restrict__ O)
{
    const int bh = blockIdx.z, b = bh >> 4, h = bh & 15;
    const int bm = blockIdx.x;                      // 0..15 (64-row tiles)
    const float* Pb = P  + (size_t)bh * Ssz * Ssz + (size_t)bm * 64 * Ssz;
    const float* Vb = Vm + (size_t)b * Ssz * Dm + h * DKk;
    float* Ob       = O  + (size_t)b * Ssz * Dm + h * DKk + (size_t)bm * 64 * Dm;
    const int Kmax = (bm + 1) * 64;                 // causal: probs zero beyond

    __shared__ float As[16][64], Bs[16][64];
    const int tid = threadIdx.x;
    const int tx = tid & 15, ty = tid >> 4;
    const int arow = tid >> 2,  acol = (tid & 3) * 4;
    const int brow = tid >> 4,  bcol = (tid & 15) * 4;

    float acc[4][4];
    #pragma unroll
    for (int i = 0; i < 4; i++)
        #pragma unroll
        for (int j = 0; j < 4; j++) acc[i][j] = 0.f;

    for (int k0 = 0; k0 < Kmax; k0 += 16) {
        float4 a4 = *(const float4*)(Pb + (size_t)arow * Ssz + k0 + acol);
        float4 b4 = *(const float4*)(Vb + (size_t)(k0 + brow) * Dm + bcol);
        As[acol+0][arow] = a4.x; As[acol+1][arow] = a4.y;
        As[acol+2][arow] = a4.z; As[acol+3][arow] = a4.w;
        *(float4*)&Bs[brow][bcol] = b4;
        __syncthreads();
        #pragma unroll
        for (int k = 0; k < 16; k++) {
            float a[4], bb[4];
            *(float4*)a  = *(const float4*)&As[k][ty * 4];
            *(float4*)bb = *(const float4*)&Bs[k][tx * 4];
            #pragma unroll
            for (int i = 0; i < 4; i++)
                #pragma unroll
                for (int j = 0; j < 4; j++) acc[i][j] = fmaf(a[i], bb[j], acc[i][j]);
        }
        __syncthreads();
    }
    #pragma unroll
    for (int i = 0; i < 4; i++) {
        float4 v; v.x = acc[i][0]; v.y = acc[i][1]; v.z = acc[i][2]; v.w = acc[i][3];
        *(float4*)(Ob + (size_t)(ty * 4 + i) * Dm + tx * 4) = v;
    }
}

// ---------------- driver -----------------------------------------------------
extern "C" void kernel_launch(void* const* d_in, const int* in_sizes, int n_in,
                              void* d_out, int out_size)
{
    const int*   ids  = (const int*)  d_in[0];
    const float* tok  = (const float*)d_in[1];
    const float* pos  = (const float*)d_in[2];
    const float* Wq   = (const float*)d_in[3];
    const float* bq   = (const float*)d_in[4];
    const float* Wk   = (const float*)d_in[5];
    const float* bk   = (const float*)d_in[6];
    const float* Wv   = (const float*)d_in[7];
    const float* bv   = (const float*)d_in[8];
    const float* Wo   = (const float*)d_in[9];
    const float* bo   = (const float*)d_in[10];
    const float* W1   = (const float*)d_in[11];
    const float* b1   = (const float*)d_in[12];
    const float* W2   = (const float*)d_in[13];
    const float* b2   = (const float*)d_in[14];
    const float* ln1g = (const float*)d_in[15];
    const float* ln1b = (const float*)d_in[16];
    const float* ln2g = (const float*)d_in[17];
    const float* ln2b = (const float*)d_in[18];
    const float* lnfg = (const float*)d_in[19];
    const float* lnfb = (const float*)d_in[20];
    const float* Wout = (const float*)d_in[21];
    const float* bout = (const float*)d_in[22];
    float* out = (float*)d_out;

    float *x, *h, *q, *k, *v, *o, *ff, *sc;
    cudaGetSymbolAddress((void**)&x,  g_x);
    cudaGetSymbolAddress((void**)&h,  g_h);
    cudaGetSymbolAddress((void**)&q,  g_q);
    cudaGetSymbolAddress((void**)&k,  g_k);
    cudaGetSymbolAddress((void**)&v,  g_v);
    cudaGetSymbolAddress((void**)&o,  g_o);
    cudaGetSymbolAddress((void**)&ff, g_ff);
    cudaGetSymbolAddress((void**)&sc, g_sc);

    embed_k<<<TOK, 256>>>(ids, tok, pos, x);

    const dim3 gProj(Dm / 64,  TOK / 128);   // N=1024 GEMMs: 128x64 tiles, 256 blocks
    const dim3 gFfn1(Ff / 128, TOK / 128);   // N=4096: 128x128 tiles, 512 blocks
    const dim3 gLogit(Vv / 128, TOK / 128);  // N=32000: 4000 blocks
    const dim3 gScore(Ssz / 128, Ssz / 128, Bsz * Hh);
    const dim3 gAv(Ssz / 64, 1, Bsz * Hh);

    for (int l = 0; l < Ll; l++) {
        const size_t oD  = (size_t)l * Dm * Dm;
        const size_t oF  = (size_t)l * Dm * Ff;
        const size_t oDb = (size_t)l * Dm;
        const size_t oFb = (size_t)l * Ff;

        layernorm_k<<<TOK, 256>>>(x, ln1g + oDb, ln1b + oDb, h);
        sgemm_k<128,64,8,8,4,F_BIAS><<<gProj, 256>>>(h, Dm, Wq + oD, Dm, bq + oDb, nullptr, q, Dm, Dm);
        sgemm_k<128,64,8,8,4,F_BIAS><<<gProj, 256>>>(h, Dm, Wk + oD, Dm, bk + oDb, nullptr, k, Dm, Dm);
        sgemm_k<128,64,8,8,4,F_BIAS><<<gProj, 256>>>(h, Dm, Wv + oD, Dm, bv + oDb, nullptr, v, Dm, Dm);

        attn_scores_k<<<gScore, 256>>>(q, k, sc);
        softmax_k<<<(Bsz * Hh * Ssz) / 8, 256>>>(sc);
        attn_av_k<<<gAv, 256>>>(sc, v, o);

        sgemm_k<128,64,8,8,4,F_BIAS|F_RES><<<gProj, 256>>>(o, Dm, Wo + oD, Dm, bo + oDb, x, x, Dm, Dm);

        layernorm_k<<<TOK, 256>>>(x, ln2g + oDb, ln2b + oDb, h);
        sgemm_k<128,128,8,8,8,F_BIAS|F_RELU><<<gFfn1, 256>>>(h, Dm, W1 + oF, Ff, b1 + oFb, nullptr, ff, Ff, Dm);
        sgemm_k<128,64,8,8,4,F_BIAS|F_RES><<<gProj, 256>>>(ff, Ff, W2 + oF, Dm, b2 + oDb, x, x, Dm, Ff);
    }

    layernorm_k<<<TOK, 256>>>(x, lnfg, lnfb, h);
    sgemm_k<128,128,8,8,8,F_BIAS><<<gLogit, 256>>>(h, Dm, Wout, Vv, bout, nullptr, out, Vv, Dm);
}

// round 7
// speedup vs baseline: 1.7497x; 1.7497x over previous
#include <cuda_runtime.h>
#include <cuda_bf16.h>
#include <mma.h>
#include <cstdint>
#include <cstddef>

using namespace nvcuda;

#define Bsz 2
#define Ssz 1024
#define Dm  1024
#define Hh  16
#define DKk 64
#define Ff  4096
#define Vv  32000
#define Ll  8
#define TOK (Bsz*Ssz)

// ===================== scratch ==============================================
__device__ float g_x [TOK*Dm];
__device__ float g_h [TOK*Dm];
__device__ float g_q [TOK*Dm];
__device__ float g_k [TOK*Dm];
__device__ float g_v [TOK*Dm];
__device__ float g_o [TOK*Dm];
__device__ float g_ff[TOK*Ff];
__device__ float g_sc[(size_t)Bsz*Hh*Ssz*Ssz];

// converted weights: per weight class, per layer: hi [N,K] bf16 then lo [N,K]
#define SQW ((size_t)2*Dm*Dm)
#define SW1 ((size_t)2*Dm*Ff)
#define OFF_Q  ((size_t)0)
#define OFF_K  (OFF_Q  + (size_t)Ll*SQW)
#define OFF_V  (OFF_K  + (size_t)Ll*SQW)
#define OFF_O  (OFF_V  + (size_t)Ll*SQW)
#define OFF_W1 (OFF_O  + (size_t)Ll*SQW)
#define OFF_W2 (OFF_W1 + (size_t)Ll*SW1)
#define OFF_WO (OFF_W2 + (size_t)Ll*SW1)
#define WC_TOTAL (OFF_WO + (size_t)2*Dm*Vv)
__device__ __nv_bfloat16 g_wc[WC_TOTAL];

// ======= weight convert: W [K,N] fp32 -> hi/lo [N,K] bf16 (transpose) =======
__global__ __launch_bounds__(256) void convert_w_k(
    const float* __restrict__ W, __nv_bfloat16* __restrict__ out, int Kd, int Nd)
{
    __shared__ float t[32][33];
    const int l = blockIdx.z;
    const float* Wl = W + (size_t)l * Kd * Nd;
    __nv_bfloat16* hi = out + (size_t)l * 2 * Kd * Nd;
    __nv_bfloat16* lo = hi + (size_t)Kd * Nd;
    const int nb = blockIdx.x * 32, kb = blockIdx.y * 32;
    const int tx = threadIdx.x & 31, ty = threadIdx.x >> 5;   // 32 x 8
    #pragma unroll
    for (int j = 0; j < 32; j += 8)
        t[ty + j][tx] = Wl[(size_t)(kb + ty + j) * Nd + nb + tx];
    __syncthreads();
    #pragma unroll
    for (int j = 0; j < 32; j += 8) {
        const int n = nb + ty + j, k = kb + tx;
        float v = t[tx][ty + j];
        __nv_bfloat16 h  = __float2bfloat16(v);
        __nv_bfloat16 l2 = __float2bfloat16(v - __bfloat162float(h));
        hi[(size_t)n * Kd + k] = h;
        lo[(size_t)n * Kd + k] = l2;
    }
}

// ===================== HMMA GEMM (bf16x3 split, mma.sync via wmma) ==========
// C[M,N] = A[M,K](fp32) @ B^T (+bias)(+res)(relu); B pre-split hi/lo [N,K].
#define F_BIAS 1
#define F_RES  2
#define F_RELU 4

struct GemmArgs {
    const float* A;
    const __nv_bfloat16* Bhi[3];
    const __nv_bfloat16* Blo[3];
    const float* bias[3];
    const float* Res[3];
    float* C[3];
    int K;
    int ldc;
};

template<int BN, int FLAGS>
__global__ __launch_bounds__(256) void hmma_gemm_k(GemmArgs ga)
{
    constexpr int BM = 128, BK = 32, PIT = 40;    // 80B pitch: ldmatrix conflict-free
    constexpr int WN = BN / 2;                     // warp N extent
    constexpr int NT = WN / 16;                    // n sub-tiles per warp
    constexpr int ASLOT = BM * BK / 4 / 256;       // float4 per thread (=4)
    constexpr int BSLOT = BN * BK / 8 / 256;       // uint4 per thread (128->2, 64->1)
    extern __shared__ char sm[];
    __nv_bfloat16* Ah  = (__nv_bfloat16*)sm;       // [BM][PIT]
    __nv_bfloat16* Al  = Ah  + BM * PIT;
    __nv_bfloat16* Bsh = Al  + BM * PIT;           // [BN][PIT]
    __nv_bfloat16* Bsl = Bsh + BN * PIT;

    const int tid = threadIdx.x, wid = tid >> 5;
    const int z = blockIdx.z;
    const int Kd = ga.K;
    const float* A = ga.A + (size_t)blockIdx.y * BM * Kd;
    const __nv_bfloat16* Bh = ga.Bhi[z] + (size_t)blockIdx.x * BN * Kd;
    const __nv_bfloat16* Bl = ga.Blo[z] + (size_t)blockIdx.x * BN * Kd;
    const int wm = wid & 3, wn = wid >> 2;

    wmma::fragment<wmma::accumulator, 16, 16, 16, float> acc[2][NT];
    #pragma unroll
    for (int i = 0; i < 2; i++)
        #pragma unroll
        for (int j = 0; j < NT; j++) wmma::fill_fragment(acc[i][j], 0.0f);

    float aR[ASLOT * 4];
    uint4 bhR[BSLOT], blR[BSLOT];

    auto loadg = [&](int k0) {
        #pragma unroll
        for (int s = 0; s < ASLOT; s++) {
            const int slot = tid + s * 256;
            const int r = slot >> 3, c4 = slot & 7;
            *(float4*)&aR[s * 4] = *(const float4*)(A + (size_t)r * Kd + k0 + c4 * 4);
        }
        #pragma unroll
        for (int s = 0; s < BSLOT; s++) {
            const int slot = tid + s * 256;
            const int r = slot >> 2, c8 = slot & 3;
            bhR[s] = *(const uint4*)(Bh + (size_t)r * Kd + k0 + c8 * 8);
            blR[s] = *(const uint4*)(Bl + (size_t)r * Kd + k0 + c8 * 8);
        }
    };
    auto store_s = [&]() {
        #pragma unroll
        for (int s = 0; s < ASLOT; s++) {
            const int slot = tid + s * 256;
            const int r = slot >> 3, c4 = slot & 7;
            __nv_bfloat16 h[4], l[4];
            #pragma unroll
            for (int e = 0; e < 4; e++) {
                const float v = aR[s * 4 + e];
                h[e] = __float2bfloat16(v);
                l[e] = __float2bfloat16(v - __bfloat162float(h[e]));
            }
            *(uint2*)&Ah[r * PIT + c4 * 4] = *(uint2*)h;
            *(uint2*)&Al[r * PIT + c4 * 4] = *(uint2*)l;
        }
        #pragma unroll
        for (int s = 0; s < BSLOT; s++) {
            const int slot = tid + s * 256;
            const int r = slot >> 2, c8 = slot & 3;
            *(uint4*)&Bsh[r * PIT + c8 * 8] = bhR[s];
            *(uint4*)&Bsl[r * PIT + c8 * 8] = blR[s];
        }
    };

    loadg(0); store_s(); __syncthreads();
    const int nst = Kd / BK;
    for (int i = 0; i < nst; i++) {
        if (i + 1 < nst) loadg((i + 1) * BK);       // overlap LDG with MMA below
        #pragma unroll
        for (int kk = 0; kk < BK; kk += 16) {
            wmma::fragment<wmma::matrix_a, 16, 16, 16, __nv_bfloat16, wmma::row_major> fah[2], fal[2];
            wmma::fragment<wmma::matrix_b, 16, 16, 16, __nv_bfloat16, wmma::col_major> fbh[NT], fbl[NT];
            #pragma unroll
            for (int ii = 0; ii < 2; ii++) {
                wmma::load_matrix_sync(fah[ii], Ah + (wm * 32 + ii * 16) * PIT + kk, PIT);
                wmma::load_matrix_sync(fal[ii], Al + (wm * 32 + ii * 16) * PIT + kk, PIT);
            }
            #pragma unroll
            for (int j = 0; j < NT; j++) {
                wmma::load_matrix_sync(fbh[j], Bsh + (wn * WN + j * 16) * PIT + kk, PIT);
                wmma::load_matrix_sync(fbl[j], Bsl + (wn * WN + j * 16) * PIT + kk, PIT);
            }
            #pragma unroll
            for (int ii = 0; ii < 2; ii++)
                #pragma unroll
                for (int j = 0; j < NT; j++) {
                    wmma::mma_sync(acc[ii][j], fah[ii], fbh[j], acc[ii][j]);
                    wmma::mma_sync(acc[ii][j], fah[ii], fbl[j], acc[ii][j]);
                    wmma::mma_sync(acc[ii][j], fal[ii], fbh[j], acc[ii][j]);
                }
        }
        __syncthreads();
        if (i + 1 < nst) { store_s(); __syncthreads(); }
    }

    // epilogue: acc -> SMEM staging -> coalesced fp32 STG (bias/res/relu)
    constexpr int SP = BN + 4;
    float* st = (float*)sm;                        // [BM][SP]
    #pragma unroll
    for (int ii = 0; ii < 2; ii++)
        #pragma unroll
        for (int j = 0; j < NT; j++)
            wmma::store_matrix_sync(st + (wm * 32 + ii * 16) * SP + wn * WN + j * 16,
                                    acc[ii][j], SP, wmma::mem_row_major);
    __syncthreads();

    float* C = ga.C[z] + (size_t)blockIdx.y * BM * ga.ldc + (size_t)blockIdx.x * BN;
    const float* bias = ga.bias[z] + (size_t)blockIdx.x * BN;
    const float* R = (FLAGS & F_RES)
        ? (ga.Res[z] + (size_t)blockIdx.y * BM * ga.ldc + (size_t)blockIdx.x * BN) : nullptr;
    #pragma unroll
    for (int jj = 0; jj < BM * BN / 1024; jj++) {
        const int idx = tid + jj * 256;
        const int r = idx / (BN / 4), c4 = (idx % (BN / 4)) * 4;
        float4 v;
        v.x = st[r * SP + c4 + 0]; v.y = st[r * SP + c4 + 1];
        v.z = st[r * SP + c4 + 2]; v.w = st[r * SP + c4 + 3];
        if (FLAGS & F_BIAS) {
            float4 b4 = *(const float4*)(bias + c4);
            v.x += b4.x; v.y += b4.y; v.z += b4.z; v.w += b4.w;
        }
        if (FLAGS & F_RES) {
            float4 r4 = *(const float4*)(R + (size_t)r * ga.ldc + c4);
            v.x += r4.x; v.y += r4.y; v.z += r4.z; v.w += r4.w;
        }
        if (FLAGS & F_RELU) {
            v.x = fmaxf(v.x, 0.f); v.y = fmaxf(v.y, 0.f);
            v.z = fmaxf(v.z, 0.f); v.w = fmaxf(v.w, 0.f);
        }
        *(float4*)(C + (size_t)r * ga.ldc + c4) = v;
    }
}

// smem: max(tile buffers, staging)
#define SMEM_B128 (128 * 132 * 4)          // 67584 (> 40960 tiles)
#define SMEM_B64  (128 * 68 * 4)           // 34816 (> 30720 tiles)

// ===================== embedding / layernorm ================================
__global__ __launch_bounds__(256) void embed_k(
    const int* __restrict__ ids, const float* __restrict__ tok,
    const float* __restrict__ pos, float* __restrict__ x)
{
    const int row = blockIdx.x;
    const int s   = row & (Ssz - 1);
    const int id  = ids[row];
    const int t   = threadIdx.x;
    float4 tv = *(const float4*)(tok + (size_t)id * Dm + t * 4);
    float4 pv = *(const float4*)(pos + (size_t)s  * Dm + t * 4);
    float4 o; o.x = tv.x + pv.x; o.y = tv.y + pv.y; o.z = tv.z + pv.z; o.w = tv.w + pv.w;
    *(float4*)(x + (size_t)row * Dm + t * 4) = o;
}

__global__ __launch_bounds__(256) void layernorm_k(
    const float* __restrict__ x, const float* __restrict__ g,
    const float* __restrict__ be, float* __restrict__ out)
{
    const int row = blockIdx.x;
    const int t   = threadIdx.x;
    const float* xr = x + (size_t)row * Dm;
    float4 v = *(const float4*)(xr + t * 4);
    float s  = v.x + v.y + v.z + v.w;
    float ss = v.x*v.x + v.y*v.y + v.z*v.z + v.w*v.w;
    #pragma unroll
    for (int off = 16; off; off >>= 1) {
        s  += __shfl_xor_sync(0xffffffffu, s,  off);
        ss += __shfl_xor_sync(0xffffffffu, ss, off);
    }
    __shared__ float rs[8], rss[8];
    const int warp = t >> 5, lane = t & 31;
    if (lane == 0) { rs[warp] = s; rss[warp] = ss; }
    __syncthreads();
    s = 0.f; ss = 0.f;
    #pragma unroll
    for (int i = 0; i < 8; i++) { s += rs[i]; ss += rss[i]; }
    const float mean = s  * (1.0f / Dm);
    const float var  = ss * (1.0f / Dm) - mean * mean;
    const float rstd = rsqrtf(var + 1e-5f);
    float4 gv = *(const float4*)(g  + t * 4);
    float4 bv = *(const float4*)(be + t * 4);
    float4 o;
    o.x = (v.x - mean) * rstd * gv.x + bv.x;
    o.y = (v.y - mean) * rstd * gv.y + bv.y;
    o.z = (v.z - mean) * rstd * gv.z + bv.z;
    o.w = (v.w - mean) * rstd * gv.w + bv.w;
    *(float4*)(out + (size_t)row * Dm + t * 4) = o;
}

// ===================== attention (fp32) =====================================
__global__ __launch_bounds__(256) void attn_scores_k(
    const float* __restrict__ Q, const float* __restrict__ Kmat, float* __restrict__ Sc)
{
    const int bm = blockIdx.y, bn = blockIdx.x;
    if (bn > bm) return;
    const int bh = blockIdx.z;
    const int b = bh >> 4, h = bh & 15;
    const float* Qb = Q    + (size_t)b * Ssz * Dm + h * DKk + (size_t)bm * 128 * Dm;
    const float* Kb = Kmat + (size_t)b * Ssz * Dm + h * DKk + (size_t)bn * 128 * Dm;
    float* Cb = Sc + (size_t)bh * Ssz * Ssz;

    __shared__ float As[8][128], Bs[8][128];
    const int tid = threadIdx.x;
    const int tx = tid & 15, ty = tid >> 4;
    const int lrow = tid >> 1, lcol = (tid & 1) * 4;

    float acc[8][8];
    #pragma unroll
    for (int i = 0; i < 8; i++)
        #pragma unroll
        for (int j = 0; j < 8; j++) acc[i][j] = 0.f;

    #pragma unroll
    for (int k0 = 0; k0 < DKk; k0 += 8) {
        float4 a4 = *(const float4*)(Qb + (size_t)lrow * Dm + k0 + lcol);
        float4 b4 = *(const float4*)(Kb + (size_t)lrow * Dm + k0 + lcol);
        As[lcol+0][lrow] = a4.x; As[lcol+1][lrow] = a4.y;
        As[lcol+2][lrow] = a4.z; As[lcol+3][lrow] = a4.w;
        Bs[lcol+0][lrow] = b4.x; Bs[lcol+1][lrow] = b4.y;
        Bs[lcol+2][lrow] = b4.z; Bs[lcol+3][lrow] = b4.w;
        __syncthreads();
        #pragma unroll
        for (int k = 0; k < 8; k++) {
            float a[8], bb[8];
            #pragma unroll
            for (int i = 0; i < 8; i += 4) *(float4*)&a[i]  = *(const float4*)&As[k][ty*8 + i];
            #pragma unroll
            for (int j = 0; j < 8; j += 4) *(float4*)&bb[j] = *(const float4*)&Bs[k][tx*8 + j];
            #pragma unroll
            for (int i = 0; i < 8; i++)
                #pragma unroll
                for (int j = 0; j < 8; j++) acc[i][j] = fmaf(a[i], bb[j], acc[i][j]);
        }
        __syncthreads();
    }
    const float scale = 0.125f;
    #pragma unroll
    for (int i = 0; i < 8; i++) {
        const int q = bm * 128 + ty * 8 + i;
        #pragma unroll
        for (int j = 0; j < 8; j += 4) {
            float4 v;
            v.x = acc[i][j]   * scale; v.y = acc[i][j+1] * scale;
            v.z = acc[i][j+2] * scale; v.w = acc[i][j+3] * scale;
            *(float4*)(Cb + (size_t)q * Ssz + bn * 128 + tx * 8 + j) = v;
        }
    }
}

__global__ __launch_bounds__(256) void softmax_k(float* __restrict__ Sc)
{
    const int warp = threadIdx.x >> 5, lane = threadIdx.x & 31;
    const int row = blockIdx.x * 8 + warp;
    const int bh = row >> 10, q = row & 1023;
    float* r = Sc + (size_t)bh * Ssz * Ssz + (size_t)q * Ssz;
    const int n = q + 1;
    float vals[32];
    float m = -3.0e38f;
    #pragma unroll
    for (int i = 0; i < 32; i++) {
        const int k = lane + i * 32;
        float v = (k < n) ? r[k] : -3.0e38f;
        vals[i] = v; m = fmaxf(m, v);
    }
    #pragma unroll
    for (int off = 16; off; off >>= 1) m = fmaxf(m, __shfl_xor_sync(0xffffffffu, m, off));
    float s = 0.f;
    #pragma unroll
    for (int i = 0; i < 32; i++) { float e = __expf(vals[i] - m); vals[i] = e; s += e; }
    #pragma unroll
    for (int off = 16; off; off >>= 1) s += __shfl_xor_sync(0xffffffffu, s, off);
    const float inv = 1.0f / s;
    const int kend = ((q >> 6) + 1) << 6;
    #pragma unroll
    for (int i = 0; i < 32; i++) {
        const int k = lane + i * 32;
        if (k < kend) r[k] = (k < n) ? vals[i] * inv : 0.f;
    }
}

__global__ __launch_bounds__(256) void attn_av_k(
    const float* __restrict__ P, const float* __restrict__ Vm, float* __restrict__ O)
{
    const int bh = blockIdx.z, b = bh >> 4, h = bh & 15;
    const int bm = blockIdx.x;
    const float* Pb = P  + (size_t)bh * Ssz * Ssz + (size_t)bm * 64 * Ssz;
    const float* Vb = Vm + (size_t)b * Ssz * Dm + h * DKk;
    float* Ob       = O  + (size_t)b * Ssz * Dm + h * DKk + (size_t)bm * 64 * Dm;
    const int Kmax = (bm + 1) * 64;

    __shared__ float As[16][64], Bs[16][64];
    const int tid = threadIdx.x;
    const int tx = tid & 15, ty = tid >> 4;
    const int arow = tid >> 2,  acol = (tid & 3) * 4;
    const int brow = tid >> 4,  bcol = (tid & 15) * 4;

    float acc[4][4];
    #pragma unroll
    for (int i = 0; i < 4; i++)
        #pragma unroll
        for (int j = 0; j < 4; j++) acc[i][j] = 0.f;

    for (int k0 = 0; k0 < Kmax; k0 += 16) {
        float4 a4 = *(const float4*)(Pb + (size_t)arow * Ssz + k0 + acol);
        float4 b4 = *(const float4*)(Vb + (size_t)(k0 + brow) * Dm + bcol);
        As[acol+0][arow] = a4.x; As[acol+1][arow] = a4.y;
        As[acol+2][arow] = a4.z; As[acol+3][arow] = a4.w;
        *(float4*)&Bs[brow][bcol] = b4;
        __syncthreads();
        #pragma unroll
        for (int k = 0; k < 16; k++) {
            float a[4], bb[4];
            *(float4*)a  = *(const float4*)&As[k][ty * 4];
            *(float4*)bb = *(const float4*)&Bs[k][tx * 4];
            #pragma unroll
            for (int i = 0; i < 4; i++)
                #pragma unroll
                for (int j = 0; j < 4; j++) acc[i][j] = fmaf(a[i], bb[j], acc[i][j]);
        }
        __syncthreads();
    }
    #pragma unroll
    for (int i = 0; i < 4; i++) {
        float4 v; v.x = acc[i][0]; v.y = acc[i][1]; v.z = acc[i][2]; v.w = acc[i][3];
        *(float4*)(Ob + (size_t)(ty * 4 + i) * Dm + tx * 4) = v;
    }
}

// ===================== driver ===============================================
extern "C" void kernel_launch(void* const* d_in, const int* in_sizes, int n_in,
                              void* d_out, int out_size)
{
    const int*   ids  = (const int*)  d_in[0];
    const float* tok  = (const float*)d_in[1];
    const float* pos  = (const float*)d_in[2];
    const float* Wq   = (const float*)d_in[3];
    const float* bq   = (const float*)d_in[4];
    const float* Wk   = (const float*)d_in[5];
    const float* bk   = (const float*)d_in[6];
    const float* Wv   = (const float*)d_in[7];
    const float* bv   = (const float*)d_in[8];
    const float* Wo   = (const float*)d_in[9];
    const float* bo   = (const float*)d_in[10];
    const float* W1   = (const float*)d_in[11];
    const float* b1   = (const float*)d_in[12];
    const float* W2   = (const float*)d_in[13];
    const float* b2   = (const float*)d_in[14];
    const float* ln1g = (const float*)d_in[15];
    const float* ln1b = (const float*)d_in[16];
    const float* ln2g = (const float*)d_in[17];
    const float* ln2b = (const float*)d_in[18];
    const float* lnfg = (const float*)d_in[19];
    const float* lnfb = (const float*)d_in[20];
    const float* Wout = (const float*)d_in[21];
    const float* bout = (const float*)d_in[22];
    float* out = (float*)d_out;

    float *x, *h, *q, *k, *v, *o, *ff, *sc;
    __nv_bfloat16* wc;
    cudaGetSymbolAddress((void**)&x,  g_x);
    cudaGetSymbolAddress((void**)&h,  g_h);
    cudaGetSymbolAddress((void**)&q,  g_q);
    cudaGetSymbolAddress((void**)&k,  g_k);
    cudaGetSymbolAddress((void**)&v,  g_v);
    cudaGetSymbolAddress((void**)&o,  g_o);
    cudaGetSymbolAddress((void**)&ff, g_ff);
    cudaGetSymbolAddress((void**)&sc, g_sc);
    cudaGetSymbolAddress((void**)&wc, g_wc);

    cudaFuncSetAttribute(hmma_gemm_k<128, F_BIAS>,        cudaFuncAttributeMaxDynamicSharedMemorySize, SMEM_B128);
    cudaFuncSetAttribute(hmma_gemm_k<128, F_BIAS|F_RELU>, cudaFuncAttributeMaxDynamicSharedMemorySize, SMEM_B128);
    cudaFuncSetAttribute(hmma_gemm_k<64,  F_BIAS|F_RES>,  cudaFuncAttributeMaxDynamicSharedMemorySize, SMEM_B64);

    // weight conversion (runs every call; deterministic)
    convert_w_k<<<dim3(Dm/32, Dm/32, Ll), 256>>>(Wq,   wc + OFF_Q,  Dm, Dm);
    convert_w_k<<<dim3(Dm/32, Dm/32, Ll), 256>>>(Wk,   wc + OFF_K,  Dm, Dm);
    convert_w_k<<<dim3(Dm/32, Dm/32, Ll), 256>>>(Wv,   wc + OFF_V,  Dm, Dm);
    convert_w_k<<<dim3(Dm/32, Dm/32, Ll), 256>>>(Wo,   wc + OFF_O,  Dm, Dm);
    convert_w_k<<<dim3(Ff/32, Dm/32, Ll), 256>>>(W1,   wc + OFF_W1, Dm, Ff);
    convert_w_k<<<dim3(Dm/32, Ff/32, Ll), 256>>>(W2,   wc + OFF_W2, Ff, Dm);
    convert_w_k<<<dim3(Vv/32, Dm/32, 1),  256>>>(Wout, wc + OFF_WO, Dm, Vv);

    embed_k<<<TOK, 256>>>(ids, tok, pos, x);

    const dim3 gQKV(Dm/128, TOK/128, 3);       // 384 CTAs
    const dim3 gProj64(Dm/64, TOK/128, 1);     // 256 CTAs (BN=64)
    const dim3 gFfn1(Ff/128, TOK/128, 1);      // 512 CTAs
    const dim3 gLogit(Vv/128, TOK/128, 1);     // 4000 CTAs
    const dim3 gScore(Ssz/128, Ssz/128, Bsz*Hh);
    const dim3 gAv(Ssz/64, 1, Bsz*Hh);

    for (int l = 0; l < Ll; l++) {
        const size_t oDb = (size_t)l * Dm;
        const size_t oFb = (size_t)l * Ff;
        const size_t oq = (size_t)l * SQW, o1 = (size_t)l * SW1;

        layernorm_k<<<TOK, 256>>>(x, ln1g + oDb, ln1b + oDb, h);

        GemmArgs qa{};
        qa.A = h; qa.K = Dm; qa.ldc = Dm;
        qa.Bhi[0] = wc + OFF_Q + oq; qa.Blo[0] = qa.Bhi[0] + (size_t)Dm*Dm;
        qa.Bhi[1] = wc + OFF_K + oq; qa.Blo[1] = qa.Bhi[1] + (size_t)Dm*Dm;
        qa.Bhi[2] = wc + OFF_V + oq; qa.Blo[2] = qa.Bhi[2] + (size_t)Dm*Dm;
        qa.bias[0] = bq + oDb; qa.bias[1] = bk + oDb; qa.bias[2] = bv + oDb;
        qa.C[0] = q; qa.C[1] = k; qa.C[2] = v;
        hmma_gemm_k<128, F_BIAS><<<gQKV, 256, SMEM_B128>>>(qa);

        attn_scores_k<<<gScore, 256>>>(q, k, sc);
        softmax_k<<<(Bsz*Hh*Ssz)/8, 256>>>(sc);
        attn_av_k<<<gAv, 256>>>(sc, v, o);

        GemmArgs oa{};
        oa.A = o; oa.K = Dm; oa.ldc = Dm;
        oa.Bhi[0] = wc + OFF_O + oq; oa.Blo[0] = oa.Bhi[0] + (size_t)Dm*Dm;
        oa.bias[0] = bo + oDb; oa.Res[0] = x; oa.C[0] = x;
        hmma_gemm_k<64, F_BIAS|F_RES><<<gProj64, 256, SMEM_B64>>>(oa);

        layernorm_k<<<TOK, 256>>>(x, ln2g + oDb, ln2b + oDb, h);

        GemmArgs fa{};
        fa.A = h; fa.K = Dm; fa.ldc = Ff;
        fa.Bhi[0] = wc + OFF_W1 + o1; fa.Blo[0] = fa.Bhi[0] + (size_t)Dm*Ff;
        fa.bias[0] = b1 + oFb; fa.C[0] = ff;
        hmma_gemm_k<128, F_BIAS|F_RELU><<<gFfn1, 256, SMEM_B128>>>(fa);

        GemmArgs f2{};
        f2.A = ff; f2.K = Ff; f2.ldc = Dm;
        f2.Bhi[0] = wc + OFF_W2 + o1; f2.Blo[0] = f2.Bhi[0] + (size_t)Dm*Ff;
        f2.bias[0] = b2 + oDb; f2.Res[0] = x; f2.C[0] = x;
        hmma_gemm_k<64, F_BIAS|F_RES><<<gProj64, 256, SMEM_B64>>>(f2);
    }

    layernorm_k<<<TOK, 256>>>(x, lnfg, lnfb, h);

    GemmArgs la{};
    la.A = h; la.K = Dm; la.ldc = Vv;
    la.Bhi[0] = wc + OFF_WO; la.Blo[0] = la.Bhi[0] + (size_t)Dm*Vv;
    la.bias[0] = bout; la.C[0] = out;
    hmma_gemm_k<128, F_BIAS><<<gLogit, 256, SMEM_B128>>>(la);
}

// round 8
// speedup vs baseline: 1.8689x; 1.0681x over previous
#include <cuda_runtime.h>
#include <cuda_bf16.h>
#include <mma.h>
#include <cstdint>
#include <cstddef>

using namespace nvcuda;

#define Bsz 2
#define Ssz 1024
#define Dm  1024
#define Hh  16
#define DKk 64
#define Ff  4096
#define Vv  32000
#define Ll  8
#define TOK (Bsz*Ssz)
#define BH  (Bsz*Hh)

// ===================== scratch ==============================================
__device__ float g_x [TOK*Dm];
__device__ float g_h [TOK*Dm];
__device__ float g_o [TOK*Dm];
__device__ float g_ff[TOK*Ff];
__device__ float g_sc[(size_t)BH*Ssz*Ssz];                // fp32 scores
__device__ __nv_bfloat16 g_ph[(size_t)BH*Ssz*Ssz];        // probs hi
__device__ __nv_bfloat16 g_pl[(size_t)BH*Ssz*Ssz];        // probs lo
__device__ __nv_bfloat16 g_qh[TOK*Dm], g_ql[TOK*Dm];      // head-major [B,H,S,64]
__device__ __nv_bfloat16 g_kh[TOK*Dm], g_kl[TOK*Dm];
__device__ __nv_bfloat16 g_vh[TOK*Dm], g_vl[TOK*Dm];

// converted weights: per weight class, per layer: hi [N,K] bf16 then lo [N,K]
#define SQW ((size_t)2*Dm*Dm)
#define SW1 ((size_t)2*Dm*Ff)
#define OFF_Q  ((size_t)0)
#define OFF_K  (OFF_Q  + (size_t)Ll*SQW)
#define OFF_V  (OFF_K  + (size_t)Ll*SQW)
#define OFF_O  (OFF_V  + (size_t)Ll*SQW)
#define OFF_W1 (OFF_O  + (size_t)Ll*SQW)
#define OFF_W2 (OFF_W1 + (size_t)Ll*SW1)
#define OFF_WO (OFF_W2 + (size_t)Ll*SW1)
#define WC_TOTAL (OFF_WO + (size_t)2*Dm*Vv)
__device__ __nv_bfloat16 g_wc[WC_TOTAL];

__device__ __forceinline__ void split_bf16(float v, __nv_bfloat16& h, __nv_bfloat16& l) {
    h = __float2bfloat16(v);
    l = __float2bfloat16(v - __bfloat162float(h));
}

// ======= weight convert: W [K,N] fp32 -> hi/lo [N,K] bf16 (transpose) =======
__global__ __launch_bounds__(256) void convert_w_k(
    const float* __restrict__ W, __nv_bfloat16* __restrict__ out, int Kd, int Nd)
{
    __shared__ float t[32][33];
    const int l = blockIdx.z;
    const float* Wl = W + (size_t)l * Kd * Nd;
    __nv_bfloat16* hi = out + (size_t)l * 2 * Kd * Nd;
    __nv_bfloat16* lo = hi + (size_t)Kd * Nd;
    const int nb = blockIdx.x * 32, kb = blockIdx.y * 32;
    const int tx = threadIdx.x & 31, ty = threadIdx.x >> 5;
    #pragma unroll
    for (int j = 0; j < 32; j += 8)
        t[ty + j][tx] = Wl[(size_t)(kb + ty + j) * Nd + nb + tx];
    __syncthreads();
    #pragma unroll
    for (int j = 0; j < 32; j += 8) {
        const int n = nb + ty + j, k = kb + tx;
        float v = t[tx][ty + j];
        __nv_bfloat16 h, l2; split_bf16(v, h, l2);
        hi[(size_t)n * Kd + k] = h;
        lo[(size_t)n * Kd + k] = l2;
    }
}

// ===================== HMMA GEMM (bf16x3 split) =============================
#define F_BIAS 1
#define F_RES  2
#define F_RELU 4
#define F_QKVOUT 8

struct GemmArgs {
    const float* A;
    const __nv_bfloat16* Bhi[3];
    const __nv_bfloat16* Blo[3];
    const float* bias[3];
    const float* Res[3];
    float* C[3];
    __nv_bfloat16* Chi[3];
    __nv_bfloat16* Clo[3];
    int K;
    int ldc;
};

template<int BN, int FLAGS>
__global__ __launch_bounds__(256) void hmma_gemm_k(GemmArgs ga)
{
    constexpr int BM = 128, BK = 32, PIT = 40;
    constexpr int WN = BN / 2;
    constexpr int NT = WN / 16;
    constexpr int ASLOT = BM * BK / 4 / 256;
    constexpr int BSLOT = BN * BK / 8 / 256;
    extern __shared__ char sm[];
    __nv_bfloat16* Ah  = (__nv_bfloat16*)sm;
    __nv_bfloat16* Al  = Ah  + BM * PIT;
    __nv_bfloat16* Bsh = Al  + BM * PIT;
    __nv_bfloat16* Bsl = Bsh + BN * PIT;

    const int tid = threadIdx.x, wid = tid >> 5;
    const int z = blockIdx.z;
    const int Kd = ga.K;
    const float* A = ga.A + (size_t)blockIdx.y * BM * Kd;
    const __nv_bfloat16* Bh = ga.Bhi[z] + (size_t)blockIdx.x * BN * Kd;
    const __nv_bfloat16* Bl = ga.Blo[z] + (size_t)blockIdx.x * BN * Kd;
    const int wm = wid & 3, wn = wid >> 2;

    wmma::fragment<wmma::accumulator, 16, 16, 16, float> acc[2][NT];
    #pragma unroll
    for (int i = 0; i < 2; i++)
        #pragma unroll
        for (int j = 0; j < NT; j++) wmma::fill_fragment(acc[i][j], 0.0f);

    float aR[ASLOT * 4];
    uint4 bhR[BSLOT], blR[BSLOT];

    auto loadg = [&](int k0) {
        #pragma unroll
        for (int s = 0; s < ASLOT; s++) {
            const int slot = tid + s * 256;
            const int r = slot >> 3, c4 = slot & 7;
            *(float4*)&aR[s * 4] = *(const float4*)(A + (size_t)r * Kd + k0 + c4 * 4);
        }
        #pragma unroll
        for (int s = 0; s < BSLOT; s++) {
            const int slot = tid + s * 256;
            const int r = slot >> 2, c8 = slot & 3;
            bhR[s] = *(const uint4*)(Bh + (size_t)r * Kd + k0 + c8 * 8);
            blR[s] = *(const uint4*)(Bl + (size_t)r * Kd + k0 + c8 * 8);
        }
    };
    auto store_s = [&]() {
        #pragma unroll
        for (int s = 0; s < ASLOT; s++) {
            const int slot = tid + s * 256;
            const int r = slot >> 3, c4 = slot & 7;
            __nv_bfloat16 h[4], l[4];
            #pragma unroll
            for (int e = 0; e < 4; e++) split_bf16(aR[s * 4 + e], h[e], l[e]);
            *(uint2*)&Ah[r * PIT + c4 * 4] = *(uint2*)h;
            *(uint2*)&Al[r * PIT + c4 * 4] = *(uint2*)l;
        }
        #pragma unroll
        for (int s = 0; s < BSLOT; s++) {
            const int slot = tid + s * 256;
            const int r = slot >> 2, c8 = slot & 3;
            *(uint4*)&Bsh[r * PIT + c8 * 8] = bhR[s];
            *(uint4*)&Bsl[r * PIT + c8 * 8] = blR[s];
        }
    };

    loadg(0); store_s(); __syncthreads();
    const int nst = Kd / BK;
    for (int i = 0; i < nst; i++) {
        if (i + 1 < nst) loadg((i + 1) * BK);
        #pragma unroll
        for (int kk = 0; kk < BK; kk += 16) {
            wmma::fragment<wmma::matrix_a, 16, 16, 16, __nv_bfloat16, wmma::row_major> fah[2], fal[2];
            wmma::fragment<wmma::matrix_b, 16, 16, 16, __nv_bfloat16, wmma::col_major> fbh[NT], fbl[NT];
            #pragma unroll
            for (int ii = 0; ii < 2; ii++) {
                wmma::load_matrix_sync(fah[ii], Ah + (wm * 32 + ii * 16) * PIT + kk, PIT);
                wmma::load_matrix_sync(fal[ii], Al + (wm * 32 + ii * 16) * PIT + kk, PIT);
            }
            #pragma unroll
            for (int j = 0; j < NT; j++) {
                wmma::load_matrix_sync(fbh[j], Bsh + (wn * WN + j * 16) * PIT + kk, PIT);
                wmma::load_matrix_sync(fbl[j], Bsl + (wn * WN + j * 16) * PIT + kk, PIT);
            }
            #pragma unroll
            for (int ii = 0; ii < 2; ii++)
                #pragma unroll
                for (int j = 0; j < NT; j++) {
                    wmma::mma_sync(acc[ii][j], fah[ii], fbh[j], acc[ii][j]);
                    wmma::mma_sync(acc[ii][j], fah[ii], fbl[j], acc[ii][j]);
                    wmma::mma_sync(acc[ii][j], fal[ii], fbh[j], acc[ii][j]);
                }
        }
        __syncthreads();
        if (i + 1 < nst) { store_s(); __syncthreads(); }
    }

    // epilogue: acc -> SMEM staging -> writeout
    constexpr int SP = BN + 4;
    float* st = (float*)sm;
    #pragma unroll
    for (int ii = 0; ii < 2; ii++)
        #pragma unroll
        for (int j = 0; j < NT; j++)
            wmma::store_matrix_sync(st + (wm * 32 + ii * 16) * SP + wn * WN + j * 16,
                                    acc[ii][j], SP, wmma::mem_row_major);
    __syncthreads();

    const float* bias = ga.bias[z] + (size_t)blockIdx.x * BN;
    #pragma unroll
    for (int jj = 0; jj < BM * BN / 1024; jj++) {
        const int idx = tid + jj * 256;
        const int r = idx / (BN / 4), c4 = (idx % (BN / 4)) * 4;
        float4 v;
        v.x = st[r * SP + c4 + 0]; v.y = st[r * SP + c4 + 1];
        v.z = st[r * SP + c4 + 2]; v.w = st[r * SP + c4 + 3];
        if (FLAGS & F_BIAS) {
            float4 b4 = *(const float4*)(bias + c4);
            v.x += b4.x; v.y += b4.y; v.z += b4.z; v.w += b4.w;
        }
        if (FLAGS & F_QKVOUT) {
            const int token = blockIdx.y * BM + r;
            const int bb = token >> 10, ss = token & 1023;
            const int f = blockIdx.x * BN + c4;
            const int hh = f >> 6, dk = f & 63;
            const size_t base = (((size_t)bb * Hh + hh) * Ssz + ss) * DKk + dk;
            __nv_bfloat16 h[4], l[4];
            split_bf16(v.x, h[0], l[0]); split_bf16(v.y, h[1], l[1]);
            split_bf16(v.z, h[2], l[2]); split_bf16(v.w, h[3], l[3]);
            *(uint2*)(ga.Chi[z] + base) = *(uint2*)h;
            *(uint2*)(ga.Clo[z] + base) = *(uint2*)l;
        } else {
            if (FLAGS & F_RES) {
                const float* R = ga.Res[z] + (size_t)blockIdx.y * BM * ga.ldc + (size_t)blockIdx.x * BN;
                float4 r4 = *(const float4*)(R + (size_t)r * ga.ldc + c4);
                v.x += r4.x; v.y += r4.y; v.z += r4.z; v.w += r4.w;
            }
            if (FLAGS & F_RELU) {
                v.x = fmaxf(v.x, 0.f); v.y = fmaxf(v.y, 0.f);
                v.z = fmaxf(v.z, 0.f); v.w = fmaxf(v.w, 0.f);
            }
            float* C = ga.C[z] + (size_t)blockIdx.y * BM * ga.ldc + (size_t)blockIdx.x * BN;
            *(float4*)(C + (size_t)r * ga.ldc + c4) = v;
        }
    }
}

#define SMEM_B128 (128 * 132 * 4)
#define SMEM_B64  (128 * 68 * 4)

// ===================== attention: scores via HMMA ===========================
// per (b,h): S[128,128] tile = scale * Q[128,64] @ K^T (bf16x3), skip bn>bm
#define APIT 72
#define SMEM_SCORE (4 * 128 * APIT * 2)    // Qh,Ql,Kh,Kl tiles = 73728

__global__ __launch_bounds__(256) void attn_scores_mma(
    const __nv_bfloat16* __restrict__ Qh, const __nv_bfloat16* __restrict__ Ql,
    const __nv_bfloat16* __restrict__ Kh, const __nv_bfloat16* __restrict__ Kl,
    float* __restrict__ Sc)
{
    const int bm = blockIdx.y, bn = blockIdx.x;
    if (bn > bm) return;
    const int bh = blockIdx.z;
    extern __shared__ char sm[];
    __nv_bfloat16* sQh = (__nv_bfloat16*)sm;
    __nv_bfloat16* sQl = sQh + 128 * APIT;
    __nv_bfloat16* sKh = sQl + 128 * APIT;
    __nv_bfloat16* sKl = sKh + 128 * APIT;

    const int tid = threadIdx.x, wid = tid >> 5;
    const size_t qoff = ((size_t)bh * Ssz + bm * 128) * DKk;
    const size_t koff = ((size_t)bh * Ssz + bn * 128) * DKk;
    // load 128x64 bf16 tiles (uint4 = 8 elems): 1024 slots, 4/thread/buffer
    #pragma unroll
    for (int s = 0; s < 4; s++) {
        const int slot = tid + s * 256;
        const int r = slot >> 3, c8 = slot & 7;
        *(uint4*)&sQh[r * APIT + c8 * 8] = *(const uint4*)(Qh + qoff + (size_t)r * DKk + c8 * 8);
        *(uint4*)&sQl[r * APIT + c8 * 8] = *(const uint4*)(Ql + qoff + (size_t)r * DKk + c8 * 8);
        *(uint4*)&sKh[r * APIT + c8 * 8] = *(const uint4*)(Kh + koff + (size_t)r * DKk + c8 * 8);
        *(uint4*)&sKl[r * APIT + c8 * 8] = *(const uint4*)(Kl + koff + (size_t)r * DKk + c8 * 8);
    }
    __syncthreads();

    const int wm = wid & 3, wn = wid >> 2;          // warp tile 32 x 64
    wmma::fragment<wmma::accumulator, 16, 16, 16, float> acc[2][4];
    #pragma unroll
    for (int i = 0; i < 2; i++)
        #pragma unroll
        for (int j = 0; j < 4; j++) wmma::fill_fragment(acc[i][j], 0.0f);

    #pragma unroll
    for (int kk = 0; kk < 64; kk += 16) {
        wmma::fragment<wmma::matrix_a, 16, 16, 16, __nv_bfloat16, wmma::row_major> fah[2], fal[2];
        wmma::fragment<wmma::matrix_b, 16, 16, 16, __nv_bfloat16, wmma::col_major> fbh[4], fbl[4];
        #pragma unroll
        for (int ii = 0; ii < 2; ii++) {
            wmma::load_matrix_sync(fah[ii], sQh + (wm * 32 + ii * 16) * APIT + kk, APIT);
            wmma::load_matrix_sync(fal[ii], sQl + (wm * 32 + ii * 16) * APIT + kk, APIT);
        }
        #pragma unroll
        for (int j = 0; j < 4; j++) {
            wmma::load_matrix_sync(fbh[j], sKh + (wn * 64 + j * 16) * APIT + kk, APIT);
            wmma::load_matrix_sync(fbl[j], sKl + (wn * 64 + j * 16) * APIT + kk, APIT);
        }
        #pragma unroll
        for (int ii = 0; ii < 2; ii++)
            #pragma unroll
            for (int j = 0; j < 4; j++) {
                wmma::mma_sync(acc[ii][j], fah[ii], fbh[j], acc[ii][j]);
                wmma::mma_sync(acc[ii][j], fah[ii], fbl[j], acc[ii][j]);
                wmma::mma_sync(acc[ii][j], fal[ii], fbh[j], acc[ii][j]);
            }
    }
    float* Cb = Sc + (size_t)bh * Ssz * Ssz + (size_t)(bm * 128) * Ssz + bn * 128;
    #pragma unroll
    for (int ii = 0; ii < 2; ii++)
        #pragma unroll
        for (int j = 0; j < 4; j++) {
            #pragma unroll
            for (int t = 0; t < acc[ii][j].num_elements; t++) acc[ii][j].x[t] *= 0.125f;
            wmma::store_matrix_sync(Cb + (size_t)(wm * 32 + ii * 16) * Ssz + wn * 64 + j * 16,
                                    acc[ii][j], Ssz, wmma::mem_row_major);
        }
}

// ===================== softmax: fp32 in -> bf16 hi/lo probs =================
__global__ __launch_bounds__(256) void softmax_k(
    const float* __restrict__ Sc, __nv_bfloat16* __restrict__ Ph,
    __nv_bfloat16* __restrict__ Pl)
{
    const int warp = threadIdx.x >> 5, lane = threadIdx.x & 31;
    const int row = blockIdx.x * 8 + warp;
    const int bh = row >> 10, q = row & 1023;
    const float* r = Sc + (size_t)bh * Ssz * Ssz + (size_t)q * Ssz;
    const int n = q + 1;
    float vals[32];
    float m = -3.0e38f;
    #pragma unroll
    for (int i = 0; i < 32; i++) {
        const int k = lane + i * 32;
        float v = (k < n) ? r[k] : -3.0e38f;
        vals[i] = v; m = fmaxf(m, v);
    }
    #pragma unroll
    for (int off = 16; off; off >>= 1) m = fmaxf(m, __shfl_xor_sync(0xffffffffu, m, off));
    float s = 0.f;
    #pragma unroll
    for (int i = 0; i < 32; i++) { float e = __expf(vals[i] - m); vals[i] = e; s += e; }
    #pragma unroll
    for (int off = 16; off; off >>= 1) s += __shfl_xor_sync(0xffffffffu, s, off);
    const float inv = 1.0f / s;
    const int kend = ((q >> 7) + 1) << 7;            // 128-aligned for MMA tiles
    __nv_bfloat16* ph = Ph + (size_t)bh * Ssz * Ssz + (size_t)q * Ssz;
    __nv_bfloat16* pl = Pl + (size_t)bh * Ssz * Ssz + (size_t)q * Ssz;
    #pragma unroll
    for (int i = 0; i < 32; i++) {
        const int k = lane + i * 32;
        if (k < kend) {
            float p = (k < n) ? vals[i] * inv : 0.f;
            __nv_bfloat16 h, l; split_bf16(p, h, l);
            ph[k] = h; pl[k] = l;
        }
    }
}

// ===================== O = P @ V via HMMA (bf16x3, causal-truncated) ========
#define SMEM_AV ((128 * APIT * 2 + 64 * APIT * 2) * 2)   // P hi/lo + V hi/lo = 55296

__global__ __launch_bounds__(256) void attn_av_mma(
    const __nv_bfloat16* __restrict__ Ph, const __nv_bfloat16* __restrict__ Pl,
    const __nv_bfloat16* __restrict__ Vh, const __nv_bfloat16* __restrict__ Vl,
    float* __restrict__ O)
{
    const int bh = blockIdx.z, bb = bh >> 4, hh = bh & 15;
    const int bm = blockIdx.x;                       // 128-row q tiles
    extern __shared__ char sm[];
    __nv_bfloat16* sPh = (__nv_bfloat16*)sm;         // [128][APIT]
    __nv_bfloat16* sPl = sPh + 128 * APIT;
    __nv_bfloat16* sVh = sPl + 128 * APIT;           // [64][APIT]
    __nv_bfloat16* sVl = sVh + 64 * APIT;

    const int tid = threadIdx.x, wid = tid >> 5;     // 8 warps, 16 rows each
    const __nv_bfloat16* Pbh = Ph + (size_t)bh * Ssz * Ssz + (size_t)(bm * 128) * Ssz;
    const __nv_bfloat16* Pbl = Pl + (size_t)bh * Ssz * Ssz + (size_t)(bm * 128) * Ssz;
    const __nv_bfloat16* Vbh = Vh + (size_t)bh * Ssz * DKk;
    const __nv_bfloat16* Vbl = Vl + (size_t)bh * Ssz * DKk;

    wmma::fragment<wmma::accumulator, 16, 16, 16, float> acc[4];
    #pragma unroll
    for (int j = 0; j < 4; j++) wmma::fill_fragment(acc[j], 0.0f);

    const int Kmax = (bm + 1) * 128;
    for (int k0 = 0; k0 < Kmax; k0 += 64) {
        // P tile 128x64 (8 bf16/uint4): 1024 slots, 4/thread/buffer
        #pragma unroll
        for (int s = 0; s < 4; s++) {
            const int slot = tid + s * 256;
            const int r = slot >> 3, c8 = slot & 7;
            *(uint4*)&sPh[r * APIT + c8 * 8] = *(const uint4*)(Pbh + (size_t)r * Ssz + k0 + c8 * 8);
            *(uint4*)&sPl[r * APIT + c8 * 8] = *(const uint4*)(Pbl + (size_t)r * Ssz + k0 + c8 * 8);
        }
        // V tile 64x64: 512 slots, 2/thread/buffer
        #pragma unroll
        for (int s = 0; s < 2; s++) {
            const int slot = tid + s * 256;
            const int r = slot >> 3, c8 = slot & 7;
            *(uint4*)&sVh[r * APIT + c8 * 8] = *(const uint4*)(Vbh + (size_t)(k0 + r) * DKk + c8 * 8);
            *(uint4*)&sVl[r * APIT + c8 * 8] = *(const uint4*)(Vbl + (size_t)(k0 + r) * DKk + c8 * 8);
        }
        __syncthreads();
        #pragma unroll
        for (int kk = 0; kk < 64; kk += 16) {
            wmma::fragment<wmma::matrix_a, 16, 16, 16, __nv_bfloat16, wmma::row_major> fah, fal;
            wmma::fragment<wmma::matrix_b, 16, 16, 16, __nv_bfloat16, wmma::row_major> fbh[4], fbl[4];
            wmma::load_matrix_sync(fah, sPh + (wid * 16) * APIT + kk, APIT);
            wmma::load_matrix_sync(fal, sPl + (wid * 16) * APIT + kk, APIT);
            #pragma unroll
            for (int j = 0; j < 4; j++) {
                wmma::load_matrix_sync(fbh[j], sVh + kk * APIT + j * 16, APIT);
                wmma::load_matrix_sync(fbl[j], sVl + kk * APIT + j * 16, APIT);
            }
            #pragma unroll
            for (int j = 0; j < 4; j++) {
                wmma::mma_sync(acc[j], fah, fbh[j], acc[j]);
                wmma::mma_sync(acc[j], fah, fbl[j], acc[j]);
                wmma::mma_sync(acc[j], fal, fbh[j], acc[j]);
            }
        }
        __syncthreads();
    }
    // write o token-major fp32: row s = bm*128 + wid*16 + i, col h*64 + j*16
    float* Ob = O + ((size_t)bb * Ssz + bm * 128 + wid * 16) * Dm + hh * DKk;
    #pragma unroll
    for (int j = 0; j < 4; j++)
        wmma::store_matrix_sync(Ob + j * 16, acc[j], Dm, wmma::mem_row_major);
}

// ===================== embedding / layernorm ================================
__global__ __launch_bounds__(256) void embed_k(
    const int* __restrict__ ids, const float* __restrict__ tok,
    const float* __restrict__ pos, float* __restrict__ x)
{
    const int row = blockIdx.x;
    const int s   = row & (Ssz - 1);
    const int id  = ids[row];
    const int t   = threadIdx.x;
    float4 tv = *(const float4*)(tok + (size_t)id * Dm + t * 4);
    float4 pv = *(const float4*)(pos + (size_t)s  * Dm + t * 4);
    float4 o; o.x = tv.x + pv.x; o.y = tv.y + pv.y; o.z = tv.z + pv.z; o.w = tv.w + pv.w;
    *(float4*)(x + (size_t)row * Dm + t * 4) = o;
}

__global__ __launch_bounds__(256) void layernorm_k(
    const float* __restrict__ x, const float* __restrict__ g,
    const float* __restrict__ be, float* __restrict__ out)
{
    const int row = blockIdx.x;
    const int t   = threadIdx.x;
    const float* xr = x + (size_t)row * Dm;
    float4 v = *(const float4*)(xr + t * 4);
    float s  = v.x + v.y + v.z + v.w;
    float ss = v.x*v.x + v.y*v.y + v.z*v.z + v.w*v.w;
    #pragma unroll
    for (int off = 16; off; off >>= 1) {
        s  += __shfl_xor_sync(0xffffffffu, s,  off);
        ss += __shfl_xor_sync(0xffffffffu, ss, off);
    }
    __shared__ float rs[8], rss[8];
    const int warp = t >> 5, lane = t & 31;
    if (lane == 0) { rs[warp] = s; rss[warp] = ss; }
    __syncthreads();
    s = 0.f; ss = 0.f;
    #pragma unroll
    for (int i = 0; i < 8; i++) { s += rs[i]; ss += rss[i]; }
    const float mean = s  * (1.0f / Dm);
    const float var  = ss * (1.0f / Dm) - mean * mean;
    const float rstd = rsqrtf(var + 1e-5f);
    float4 gv = *(const float4*)(g  + t * 4);
    float4 bv = *(const float4*)(be + t * 4);
    float4 o;
    o.x = (v.x - mean) * rstd * gv.x + bv.x;
    o.y = (v.y - mean) * rstd * gv.y + bv.y;
    o.z = (v.z - mean) * rstd * gv.z + bv.z;
    o.w = (v.w - mean) * rstd * gv.w + bv.w;
    *(float4*)(out + (size_t)row * Dm + t * 4) = o;
}

// ===================== driver ===============================================
extern "C" void kernel_launch(void* const* d_in, const int* in_sizes, int n_in,
                              void* d_out, int out_size)
{
    const int*   ids  = (const int*)  d_in[0];
    const float* tok  = (const float*)d_in[1];
    const float* pos  = (const float*)d_in[2];
    const float* Wq   = (const float*)d_in[3];
    const float* bq   = (const float*)d_in[4];
    const float* Wk   = (const float*)d_in[5];
    const float* bk   = (const float*)d_in[6];
    const float* Wv   = (const float*)d_in[7];
    const float* bv   = (const float*)d_in[8];
    const float* Wo   = (const float*)d_in[9];
    const float* bo   = (const float*)d_in[10];
    const float* W1   = (const float*)d_in[11];
    const float* b1   = (const float*)d_in[12];
    const float* W2   = (const float*)d_in[13];
    const float* b2   = (const float*)d_in[14];
    const float* ln1g = (const float*)d_in[15];
    const float* ln1b = (const float*)d_in[16];
    const float* ln2g = (const float*)d_in[17];
    const float* ln2b = (const float*)d_in[18];
    const float* lnfg = (const float*)d_in[19];
    const float* lnfb = (const float*)d_in[20];
    const float* Wout = (const float*)d_in[21];
    const float* bout = (const float*)d_in[22];
    float* out = (float*)d_out;

    float *x, *h, *o, *ff, *sc;
    __nv_bfloat16 *wc, *qh, *ql, *kh, *kl, *vh, *vl, *ph, *pl;
    cudaGetSymbolAddress((void**)&x,  g_x);
    cudaGetSymbolAddress((void**)&h,  g_h);
    cudaGetSymbolAddress((void**)&o,  g_o);
    cudaGetSymbolAddress((void**)&ff, g_ff);
    cudaGetSymbolAddress((void**)&sc, g_sc);
    cudaGetSymbolAddress((void**)&wc, g_wc);
    cudaGetSymbolAddress((void**)&qh, g_qh); cudaGetSymbolAddress((void**)&ql, g_ql);
    cudaGetSymbolAddress((void**)&kh, g_kh); cudaGetSymbolAddress((void**)&kl, g_kl);
    cudaGetSymbolAddress((void**)&vh, g_vh); cudaGetSymbolAddress((void**)&vl, g_vl);
    cudaGetSymbolAddress((void**)&ph, g_ph); cudaGetSymbolAddress((void**)&pl, g_pl);

    cudaFuncSetAttribute(hmma_gemm_k<128, F_BIAS>,          cudaFuncAttributeMaxDynamicSharedMemorySize, SMEM_B128);
    cudaFuncSetAttribute(hmma_gemm_k<128, F_BIAS|F_QKVOUT>, cudaFuncAttributeMaxDynamicSharedMemorySize, SMEM_B128);
    cudaFuncSetAttribute(hmma_gemm_k<128, F_BIAS|F_RELU>,   cudaFuncAttributeMaxDynamicSharedMemorySize, SMEM_B128);
    cudaFuncSetAttribute(hmma_gemm_k<64,  F_BIAS|F_RES>,    cudaFuncAttributeMaxDynamicSharedMemorySize, SMEM_B64);
    cudaFuncSetAttribute(attn_scores_mma, cudaFuncAttributeMaxDynamicSharedMemorySize, SMEM_SCORE);
    cudaFuncSetAttribute(attn_av_mma,     cudaFuncAttributeMaxDynamicSharedMemorySize, SMEM_AV);

    convert_w_k<<<dim3(Dm/32, Dm/32, Ll), 256>>>(Wq,   wc + OFF_Q,  Dm, Dm);
    convert_w_k<<<dim3(Dm/32, Dm/32, Ll), 256>>>(Wk,   wc + OFF_K,  Dm, Dm);
    convert_w_k<<<dim3(Dm/32, Dm/32, Ll), 256>>>(Wv,   wc + OFF_V,  Dm, Dm);
    convert_w_k<<<dim3(Dm/32, Dm/32, Ll), 256>>>(Wo,   wc + OFF_O,  Dm, Dm);
    convert_w_k<<<dim3(Ff/32, Dm/32, Ll), 256>>>(W1,   wc + OFF_W1, Dm, Ff);
    convert_w_k<<<dim3(Dm/32, Ff/32, Ll), 256>>>(W2,   wc + OFF_W2, Ff, Dm);
    convert_w_k<<<dim3(Vv/32, Dm/32, 1),  256>>>(Wout, wc + OFF_WO, Dm, Vv);

    embed_k<<<TOK, 256>>>(ids, tok, pos, x);

    const dim3 gQKV(Dm/128, TOK/128, 3);
    const dim3 gProj64(Dm/64, TOK/128, 1);
    const dim3 gFfn1(Ff/128, TOK/128, 1);
    const dim3 gLogit(Vv/128, TOK/128, 1);
    const dim3 gScore(Ssz/128, Ssz/128, BH);
    const dim3 gAv(Ssz/128, 1, BH);

    for (int l = 0; l < Ll; l++) {
        const size_t oDb = (size_t)l * Dm;
        const size_t oFb = (size_t)l * Ff;
        const size_t oq = (size_t)l * SQW, o1 = (size_t)l * SW1;

        layernorm_k<<<TOK, 256>>>(x, ln1g + oDb, ln1b + oDb, h);

        GemmArgs qa{};
        qa.A = h; qa.K = Dm; qa.ldc = Dm;
        qa.Bhi[0] = wc + OFF_Q + oq; qa.Blo[0] = qa.Bhi[0] + (size_t)Dm*Dm;
        qa.Bhi[1] = wc + OFF_K + oq; qa.Blo[1] = qa.Bhi[1] + (size_t)Dm*Dm;
        qa.Bhi[2] = wc + OFF_V + oq; qa.Blo[2] = qa.Bhi[2] + (size_t)Dm*Dm;
        qa.bias[0] = bq + oDb; qa.bias[1] = bk + oDb; qa.bias[2] = bv + oDb;
        qa.Chi[0] = qh; qa.Clo[0] = ql;
        qa.Chi[1] = kh; qa.Clo[1] = kl;
        qa.Chi[2] = vh; qa.Clo[2] = vl;
        hmma_gemm_k<128, F_BIAS|F_QKVOUT><<<gQKV, 256, SMEM_B128>>>(qa);

        attn_scores_mma<<<gScore, 256, SMEM_SCORE>>>(qh, ql, kh, kl, sc);
        softmax_k<<<(BH*Ssz)/8, 256>>>(sc, ph, pl);
        attn_av_mma<<<gAv, 256, SMEM_AV>>>(ph, pl, vh, vl, o);

        GemmArgs oa{};
        oa.A = o; oa.K = Dm; oa.ldc = Dm;
        oa.Bhi[0] = wc + OFF_O + oq; oa.Blo[0] = oa.Bhi[0] + (size_t)Dm*Dm;
        oa.bias[0] = bo + oDb; oa.Res[0] = x; oa.C[0] = x;
        hmma_gemm_k<64, F_BIAS|F_RES><<<gProj64, 256, SMEM_B64>>>(oa);

        layernorm_k<<<TOK, 256>>>(x, ln2g + oDb, ln2b + oDb, h);

        GemmArgs fa{};
        fa.A = h; fa.K = Dm; fa.ldc = Ff;
        fa.Bhi[0] = wc + OFF_W1 + o1; fa.Blo[0] = fa.Bhi[0] + (size_t)Dm*Ff;
        fa.bias[0] = b1 + oFb; fa.C[0] = ff;
        hmma_gemm_k<128, F_BIAS|F_RELU><<<gFfn1, 256, SMEM_B128>>>(fa);

        GemmArgs f2{};
        f2.A = ff; f2.K = Ff; f2.ldc = Dm;
        f2.Bhi[0] = wc + OFF_W2 + o1; f2.Blo[0] = f2.Bhi[0] + (size_t)Dm*Ff;
        f2.bias[0] = b2 + oDb; f2.Res[0] = x; f2.C[0] = x;
        hmma_gemm_k<64, F_BIAS|F_RES><<<gProj64, 256, SMEM_B64>>>(f2);
    }

    layernorm_k<<<TOK, 256>>>(x, lnfg, lnfb, h);

    GemmArgs la{};
    la.A = h; la.K = Dm; la.ldc = Vv;
    la.Bhi[0] = wc + OFF_WO; la.Blo[0] = la.Bhi[0] + (size_t)Dm*Vv;
    la.bias[0] = bout; la.C[0] = out;
    hmma_gemm_k<128, F_BIAS><<<gLogit, 256, SMEM_B128>>>(la);
}

// round 9
// speedup vs baseline: 2.2703x; 1.2148x over previous
#include <cuda_runtime.h>
#include <cuda_bf16.h>
#include <mma.h>
#include <cstdint>
#include <cstddef>

using namespace nvcuda;

#define Bsz 2
#define Ssz 1024
#define Dm  1024
#define Hh  16
#define DKk 64
#define Ff  4096
#define Vv  32000
#define Ll  8
#define TOK (Bsz*Ssz)
#define BH  (Bsz*Hh)

// ===================== scratch ==============================================
__device__ float g_x [TOK*Dm];
__device__ float g_sc[(size_t)BH*Ssz*Ssz];                 // fp32 scores
__device__ __nv_bfloat16 g_hh[TOK*Dm],  g_hl[TOK*Dm];      // LN out split
__device__ __nv_bfloat16 g_oh[TOK*Dm],  g_ol[TOK*Dm];      // attn out split
__device__ __nv_bfloat16 g_ffh[TOK*Ff], g_ffl[TOK*Ff];     // FFN1 out split
__device__ __nv_bfloat16 g_ph[(size_t)BH*Ssz*Ssz];         // probs hi
__device__ __nv_bfloat16 g_pl[(size_t)BH*Ssz*Ssz];         // probs lo
__device__ __nv_bfloat16 g_qh[TOK*Dm], g_ql[TOK*Dm];       // head-major [B,H,S,64]
__device__ __nv_bfloat16 g_kh[TOK*Dm], g_kl[TOK*Dm];
__device__ __nv_bfloat16 g_vh[TOK*Dm], g_vl[TOK*Dm];

#define SQW ((size_t)2*Dm*Dm)
#define SW1 ((size_t)2*Dm*Ff)
#define OFF_Q  ((size_t)0)
#define OFF_K  (OFF_Q  + (size_t)Ll*SQW)
#define OFF_V  (OFF_K  + (size_t)Ll*SQW)
#define OFF_O  (OFF_V  + (size_t)Ll*SQW)
#define OFF_W1 (OFF_O  + (size_t)Ll*SQW)
#define OFF_W2 (OFF_W1 + (size_t)Ll*SW1)
#define OFF_WO (OFF_W2 + (size_t)Ll*SW1)
#define WC_TOTAL (OFF_WO + (size_t)2*Dm*Vv)
__device__ __nv_bfloat16 g_wc[WC_TOTAL];

__device__ __forceinline__ void split_bf16(float v, __nv_bfloat16& h, __nv_bfloat16& l) {
    h = __float2bfloat16(v);
    l = __float2bfloat16(v - __bfloat162float(h));
}
__device__ __forceinline__ void cpa16(void* s, const void* g) {
    uint32_t sa = (uint32_t)__cvta_generic_to_shared(s);
    asm volatile("cp.async.cg.shared.global [%0], [%1], 16;" :: "r"(sa), "l"(g));
}
#define CP_COMMIT() asm volatile("cp.async.commit_group;" ::: "memory")
#define CP_WAIT1()  asm volatile("cp.async.wait_group 1;" ::: "memory")
#define CP_WAIT0()  asm volatile("cp.async.wait_group 0;" ::: "memory")

// ======= weight convert: W [K,N] fp32 -> hi/lo [N,K] bf16 (transpose) =======
__global__ __launch_bounds__(256) void convert_w_k(
    const float* __restrict__ W, __nv_bfloat16* __restrict__ out, int Kd, int Nd)
{
    __shared__ float t[32][33];
    const int l = blockIdx.z;
    const float* Wl = W + (size_t)l * Kd * Nd;
    __nv_bfloat16* hi = out + (size_t)l * 2 * Kd * Nd;
    __nv_bfloat16* lo = hi + (size_t)Kd * Nd;
    const int nb = blockIdx.x * 32, kb = blockIdx.y * 32;
    const int tx = threadIdx.x & 31, ty = threadIdx.x >> 5;
    #pragma unroll
    for (int j = 0; j < 32; j += 8)
        t[ty + j][tx] = Wl[(size_t)(kb + ty + j) * Nd + nb + tx];
    __syncthreads();
    #pragma unroll
    for (int j = 0; j < 32; j += 8) {
        const int n = nb + ty + j, k = kb + tx;
        float v = t[tx][ty + j];
        __nv_bfloat16 h, l2; split_bf16(v, h, l2);
        hi[(size_t)n * Kd + k] = h;
        lo[(size_t)n * Kd + k] = l2;
    }
}

// ===================== HMMA GEMM v3 (cp.async, pre-split A) =================
#define F_BIAS 1
#define F_RES  2
#define F_RELU 4
#define F_QKVOUT 8
#define F_SPLITOUT 16

struct GemmArgs {
    const __nv_bfloat16 *Ahi, *Alo;
    const __nv_bfloat16 *Bhi[3], *Blo[3];
    const float* bias[3];
    const float* Res;
    float* C[3];
    __nv_bfloat16 *Chi[3], *Clo[3];
    int K;
    int ldc;
};

template<int BN, int FLAGS>
__global__ __launch_bounds__(256, 2) void hmma_gemm_k(GemmArgs ga)
{
    constexpr int BM = 128, BK = 32, PIT = 40;     // 80B pitch, 16B-aligned chunks
    constexpr int WN = BN / 2, NT = WN / 16;
    constexpr int ATILE = BM * PIT;
    constexpr int BTILE = BN * PIT;
    constexpr int STG = 2 * ATILE + 2 * BTILE;     // elems per stage
    extern __shared__ __nv_bfloat16 smb[];

    const int tid = threadIdx.x, wid = tid >> 5;
    const int z = blockIdx.z;
    const int Kd = ga.K;
    const __nv_bfloat16* Ah = ga.Ahi + (size_t)blockIdx.y * BM * Kd;
    const __nv_bfloat16* Al = ga.Alo + (size_t)blockIdx.y * BM * Kd;
    const __nv_bfloat16* Bh = ga.Bhi[z] + (size_t)blockIdx.x * BN * Kd;
    const __nv_bfloat16* Bl = ga.Blo[z] + (size_t)blockIdx.x * BN * Kd;
    const int wm = wid & 3, wn = wid >> 2;

    auto stage_load = [&](int buf, int k0) {
        __nv_bfloat16* s = smb + buf * STG;
        #pragma unroll
        for (int ss = 0; ss < 2; ss++) {            // A: 512 chunks per buffer
            const int slot = tid + ss * 256;
            const int r = slot >> 2, c = slot & 3;
            cpa16(&s[r * PIT + c * 8],         Ah + (size_t)r * Kd + k0 + c * 8);
            cpa16(&s[ATILE + r * PIT + c * 8], Al + (size_t)r * Kd + k0 + c * 8);
        }
        #pragma unroll
        for (int ss = 0; ss < BN / 64; ss++) {      // B: BN*4 chunks per buffer
            const int slot = tid + ss * 256;
            const int r = slot >> 2, c = slot & 3;
            cpa16(&s[2 * ATILE + r * PIT + c * 8],         Bh + (size_t)r * Kd + k0 + c * 8);
            cpa16(&s[2 * ATILE + BTILE + r * PIT + c * 8], Bl + (size_t)r * Kd + k0 + c * 8);
        }
        CP_COMMIT();
    };

    wmma::fragment<wmma::accumulator, 16, 16, 16, float> acc[2][NT];
    #pragma unroll
    for (int i = 0; i < 2; i++)
        #pragma unroll
        for (int j = 0; j < NT; j++) wmma::fill_fragment(acc[i][j], 0.0f);

    const int nst = Kd / BK;
    stage_load(0, 0);
    for (int i = 0; i < nst; i++) {
        if (i + 1 < nst) { stage_load((i + 1) & 1, (i + 1) * BK); CP_WAIT1(); }
        else             { CP_WAIT0(); }
        __syncthreads();
        const __nv_bfloat16* s = smb + (i & 1) * STG;
        const __nv_bfloat16* sAh = s;
        const __nv_bfloat16* sAl = s + ATILE;
        const __nv_bfloat16* sBh = s + 2 * ATILE;
        const __nv_bfloat16* sBl = s + 2 * ATILE + BTILE;
        #pragma unroll
        for (int kk = 0; kk < BK; kk += 16) {
            #pragma unroll
            for (int ii = 0; ii < 2; ii++) {
                wmma::fragment<wmma::matrix_a, 16, 16, 16, __nv_bfloat16, wmma::row_major> fah, fal;
                wmma::load_matrix_sync(fah, sAh + (wm * 32 + ii * 16) * PIT + kk, PIT);
                wmma::load_matrix_sync(fal, sAl + (wm * 32 + ii * 16) * PIT + kk, PIT);
                #pragma unroll
                for (int j = 0; j < NT; j++) {
                    wmma::fragment<wmma::matrix_b, 16, 16, 16, __nv_bfloat16, wmma::col_major> fbh, fbl;
                    wmma::load_matrix_sync(fbh, sBh + (wn * WN + j * 16) * PIT + kk, PIT);
                    wmma::load_matrix_sync(fbl, sBl + (wn * WN + j * 16) * PIT + kk, PIT);
                    wmma::mma_sync(acc[ii][j], fah, fbh, acc[ii][j]);
                    wmma::mma_sync(acc[ii][j], fah, fbl, acc[ii][j]);
                    wmma::mma_sync(acc[ii][j], fal, fbh, acc[ii][j]);
                }
            }
        }
        __syncthreads();
    }

    // epilogue: acc -> SMEM staging -> writeout
    constexpr int SP = BN + 4;
    float* st = (float*)smb;
    #pragma unroll
    for (int ii = 0; ii < 2; ii++)
        #pragma unroll
        for (int j = 0; j < NT; j++)
            wmma::store_matrix_sync(st + (wm * 32 + ii * 16) * SP + wn * WN + j * 16,
                                    acc[ii][j], SP, wmma::mem_row_major);
    __syncthreads();

    const float* bias = ga.bias[z] + (size_t)blockIdx.x * BN;
    #pragma unroll
    for (int jj = 0; jj < BM * BN / 1024; jj++) {
        const int idx = tid + jj * 256;
        const int r = idx / (BN / 4), c4 = (idx % (BN / 4)) * 4;
        float4 v;
        v.x = st[r * SP + c4 + 0]; v.y = st[r * SP + c4 + 1];
        v.z = st[r * SP + c4 + 2]; v.w = st[r * SP + c4 + 3];
        if (FLAGS & F_BIAS) {
            float4 b4 = *(const float4*)(bias + c4);
            v.x += b4.x; v.y += b4.y; v.z += b4.z; v.w += b4.w;
        }
        if (FLAGS & F_RELU) {
            v.x = fmaxf(v.x, 0.f); v.y = fmaxf(v.y, 0.f);
            v.z = fmaxf(v.z, 0.f); v.w = fmaxf(v.w, 0.f);
        }
        if (FLAGS & F_QKVOUT) {
            const int token = blockIdx.y * BM + r;
            const int bb = token >> 10, ss = token & 1023;
            const int f = blockIdx.x * BN + c4;
            const int hh = f >> 6, dk = f & 63;
            const size_t base = (((size_t)bb * Hh + hh) * Ssz + ss) * DKk + dk;
            __nv_bfloat16 h[4], l[4];
            split_bf16(v.x, h[0], l[0]); split_bf16(v.y, h[1], l[1]);
            split_bf16(v.z, h[2], l[2]); split_bf16(v.w, h[3], l[3]);
            *(uint2*)(ga.Chi[z] + base) = *(uint2*)h;
            *(uint2*)(ga.Clo[z] + base) = *(uint2*)l;
        } else if (FLAGS & F_SPLITOUT) {
            const size_t base = (size_t)(blockIdx.y * BM + r) * ga.ldc + blockIdx.x * BN + c4;
            __nv_bfloat16 h[4], l[4];
            split_bf16(v.x, h[0], l[0]); split_bf16(v.y, h[1], l[1]);
            split_bf16(v.z, h[2], l[2]); split_bf16(v.w, h[3], l[3]);
            *(uint2*)(ga.Chi[z] + base) = *(uint2*)h;
            *(uint2*)(ga.Clo[z] + base) = *(uint2*)l;
        } else {
            if (FLAGS & F_RES) {
                const float* R = ga.Res + (size_t)blockIdx.y * BM * ga.ldc + (size_t)blockIdx.x * BN;
                float4 r4 = *(const float4*)(R + (size_t)r * ga.ldc + c4);
                v.x += r4.x; v.y += r4.y; v.z += r4.z; v.w += r4.w;
            }
            float* C = ga.C[z] + (size_t)blockIdx.y * BM * ga.ldc + (size_t)blockIdx.x * BN;
            *(float4*)(C + (size_t)r * ga.ldc + c4) = v;
        }
    }
}

#define STG128 ((2*128*40 + 2*128*40) * 2)                 // bytes per stage, BN=128: 40960
#define SMEM_B128 (2 * STG128)                             // 81920 (> staging 67584)
#define STG64  ((2*128*40 + 2*64*40) * 2)                  // 30720
#define SMEM_B64  (2 * STG64)                              // 61440 (> staging 34816)

// ===================== attention: scores via HMMA ===========================
#define APIT 72
#define SMEM_SCORE (4 * 128 * APIT * 2)

__global__ __launch_bounds__(256) void attn_scores_mma(
    const __nv_bfloat16* __restrict__ Qh, const __nv_bfloat16* __restrict__ Ql,
    const __nv_bfloat16* __restrict__ Kh, const __nv_bfloat16* __restrict__ Kl,
    float* __restrict__ Sc)
{
    const int bm = blockIdx.y, bn = blockIdx.x;
    if (bn > bm) return;
    const int bh = blockIdx.z;
    extern __shared__ char sm[];
    __nv_bfloat16* sQh = (__nv_bfloat16*)sm;
    __nv_bfloat16* sQl = sQh + 128 * APIT;
    __nv_bfloat16* sKh = sQl + 128 * APIT;
    __nv_bfloat16* sKl = sKh + 128 * APIT;

    const int tid = threadIdx.x, wid = tid >> 5;
    const size_t qoff = ((size_t)bh * Ssz + bm * 128) * DKk;
    const size_t koff = ((size_t)bh * Ssz + bn * 128) * DKk;
    #pragma unroll
    for (int s = 0; s < 4; s++) {
        const int slot = tid + s * 256;
        const int r = slot >> 3, c8 = slot & 7;
        *(uint4*)&sQh[r * APIT + c8 * 8] = *(const uint4*)(Qh + qoff + (size_t)r * DKk + c8 * 8);
        *(uint4*)&sQl[r * APIT + c8 * 8] = *(const uint4*)(Ql + qoff + (size_t)r * DKk + c8 * 8);
        *(uint4*)&sKh[r * APIT + c8 * 8] = *(const uint4*)(Kh + koff + (size_t)r * DKk + c8 * 8);
        *(uint4*)&sKl[r * APIT + c8 * 8] = *(const uint4*)(Kl + koff + (size_t)r * DKk + c8 * 8);
    }
    __syncthreads();

    const int wm = wid & 3, wn = wid >> 2;
    wmma::fragment<wmma::accumulator, 16, 16, 16, float> acc[2][4];
    #pragma unroll
    for (int i = 0; i < 2; i++)
        #pragma unroll
        for (int j = 0; j < 4; j++) wmma::fill_fragment(acc[i][j], 0.0f);

    #pragma unroll
    for (int kk = 0; kk < 64; kk += 16) {
        wmma::fragment<wmma::matrix_a, 16, 16, 16, __nv_bfloat16, wmma::row_major> fah[2], fal[2];
        wmma::fragment<wmma::matrix_b, 16, 16, 16, __nv_bfloat16, wmma::col_major> fbh[4], fbl[4];
        #pragma unroll
        for (int ii = 0; ii < 2; ii++) {
            wmma::load_matrix_sync(fah[ii], sQh + (wm * 32 + ii * 16) * APIT + kk, APIT);
            wmma::load_matrix_sync(fal[ii], sQl + (wm * 32 + ii * 16) * APIT + kk, APIT);
        }
        #pragma unroll
        for (int j = 0; j < 4; j++) {
            wmma::load_matrix_sync(fbh[j], sKh + (wn * 64 + j * 16) * APIT + kk, APIT);
            wmma::load_matrix_sync(fbl[j], sKl + (wn * 64 + j * 16) * APIT + kk, APIT);
        }
        #pragma unroll
        for (int ii = 0; ii < 2; ii++)
            #pragma unroll
            for (int j = 0; j < 4; j++) {
                wmma::mma_sync(acc[ii][j], fah[ii], fbh[j], acc[ii][j]);
                wmma::mma_sync(acc[ii][j], fah[ii], fbl[j], acc[ii][j]);
                wmma::mma_sync(acc[ii][j], fal[ii], fbh[j], acc[ii][j]);
            }
    }
    float* Cb = Sc + (size_t)bh * Ssz * Ssz + (size_t)(bm * 128) * Ssz + bn * 128;
    #pragma unroll
    for (int ii = 0; ii < 2; ii++)
        #pragma unroll
        for (int j = 0; j < 4; j++) {
            #pragma unroll
            for (int t = 0; t < acc[ii][j].num_elements; t++) acc[ii][j].x[t] *= 0.125f;
            wmma::store_matrix_sync(Cb + (size_t)(wm * 32 + ii * 16) * Ssz + wn * 64 + j * 16,
                                    acc[ii][j], Ssz, wmma::mem_row_major);
        }
}

// ===================== softmax: fp32 in -> bf16 hi/lo probs =================
__global__ __launch_bounds__(256) void softmax_k(
    const float* __restrict__ Sc, __nv_bfloat16* __restrict__ Ph,
    __nv_bfloat16* __restrict__ Pl)
{
    const int warp = threadIdx.x >> 5, lane = threadIdx.x & 31;
    const int row = blockIdx.x * 8 + warp;
    const int bh = row >> 10, q = row & 1023;
    const float* r = Sc + (size_t)bh * Ssz * Ssz + (size_t)q * Ssz;
    const int n = q + 1;
    float vals[32];
    float m = -3.0e38f;
    #pragma unroll
    for (int i = 0; i < 32; i++) {
        const int k = lane + i * 32;
        float v = (k < n) ? r[k] : -3.0e38f;
        vals[i] = v; m = fmaxf(m, v);
    }
    #pragma unroll
    for (int off = 16; off; off >>= 1) m = fmaxf(m, __shfl_xor_sync(0xffffffffu, m, off));
    float s = 0.f;
    #pragma unroll
    for (int i = 0; i < 32; i++) { float e = __expf(vals[i] - m); vals[i] = e; s += e; }
    #pragma unroll
    for (int off = 16; off; off >>= 1) s += __shfl_xor_sync(0xffffffffu, s, off);
    const float inv = 1.0f / s;
    const int kend = ((q >> 7) + 1) << 7;
    __nv_bfloat16* ph = Ph + (size_t)bh * Ssz * Ssz + (size_t)q * Ssz;
    __nv_bfloat16* pl = Pl + (size_t)bh * Ssz * Ssz + (size_t)q * Ssz;
    #pragma unroll
    for (int i = 0; i < 32; i++) {
        const int k = lane + i * 32;
        if (k < kend) {
            float p = (k < n) ? vals[i] * inv : 0.f;
            __nv_bfloat16 h, l; split_bf16(p, h, l);
            ph[k] = h; pl[k] = l;
        }
    }
}

// ===================== O = P @ V via HMMA (split output) ====================
#define SMEM_AV ((128 * APIT * 2 + 64 * APIT * 2) * 2)

__global__ __launch_bounds__(256) void attn_av_mma(
    const __nv_bfloat16* __restrict__ Ph, const __nv_bfloat16* __restrict__ Pl,
    const __nv_bfloat16* __restrict__ Vh, const __nv_bfloat16* __restrict__ Vl,
    __nv_bfloat16* __restrict__ Oh, __nv_bfloat16* __restrict__ Ol)
{
    const int bh = blockIdx.z, bb = bh >> 4, hh = bh & 15;
    const int bm = blockIdx.x;
    extern __shared__ char sm[];
    __nv_bfloat16* sPh = (__nv_bfloat16*)sm;
    __nv_bfloat16* sPl = sPh + 128 * APIT;
    __nv_bfloat16* sVh = sPl + 128 * APIT;
    __nv_bfloat16* sVl = sVh + 64 * APIT;

    const int tid = threadIdx.x, wid = tid >> 5;
    const __nv_bfloat16* Pbh = Ph + (size_t)bh * Ssz * Ssz + (size_t)(bm * 128) * Ssz;
    const __nv_bfloat16* Pbl = Pl + (size_t)bh * Ssz * Ssz + (size_t)(bm * 128) * Ssz;
    const __nv_bfloat16* Vbh = Vh + (size_t)bh * Ssz * DKk;
    const __nv_bfloat16* Vbl = Vl + (size_t)bh * Ssz * DKk;

    wmma::fragment<wmma::accumulator, 16, 16, 16, float> acc[4];
    #pragma unroll
    for (int j = 0; j < 4; j++) wmma::fill_fragment(acc[j], 0.0f);

    const int Kmax = (bm + 1) * 128;
    for (int k0 = 0; k0 < Kmax; k0 += 64) {
        #pragma unroll
        for (int s = 0; s < 4; s++) {
            const int slot = tid + s * 256;
            const int r = slot >> 3, c8 = slot & 7;
            *(uint4*)&sPh[r * APIT + c8 * 8] = *(const uint4*)(Pbh + (size_t)r * Ssz + k0 + c8 * 8);
            *(uint4*)&sPl[r * APIT + c8 * 8] = *(const uint4*)(Pbl + (size_t)r * Ssz + k0 + c8 * 8);
        }
        #pragma unroll
        for (int s = 0; s < 2; s++) {
            const int slot = tid + s * 256;
            const int r = slot >> 3, c8 = slot & 7;
            *(uint4*)&sVh[r * APIT + c8 * 8] = *(const uint4*)(Vbh + (size_t)(k0 + r) * DKk + c8 * 8);
            *(uint4*)&sVl[r * APIT + c8 * 8] = *(const uint4*)(Vbl + (size_t)(k0 + r) * DKk + c8 * 8);
        }
        __syncthreads();
        #pragma unroll
        for (int kk = 0; kk < 64; kk += 16) {
            wmma::fragment<wmma::matrix_a, 16, 16, 16, __nv_bfloat16, wmma::row_major> fah, fal;
            wmma::fragment<wmma::matrix_b, 16, 16, 16, __nv_bfloat16, wmma::row_major> fbh[4], fbl[4];
            wmma::load_matrix_sync(fah, sPh + (wid * 16) * APIT + kk, APIT);
            wmma::load_matrix_sync(fal, sPl + (wid * 16) * APIT + kk, APIT);
            #pragma unroll
            for (int j = 0; j < 4; j++) {
                wmma::load_matrix_sync(fbh[j], sVh + kk * APIT + j * 16, APIT);
                wmma::load_matrix_sync(fbl[j], sVl + kk * APIT + j * 16, APIT);
            }
            #pragma unroll
            for (int j = 0; j < 4; j++) {
                wmma::mma_sync(acc[j], fah, fbh[j], acc[j]);
                wmma::mma_sync(acc[j], fah, fbl[j], acc[j]);
                wmma::mma_sync(acc[j], fal, fbh[j], acc[j]);
            }
        }
        __syncthreads();
    }
    // stage fp32, then split-write token-major bf16 hi/lo
    float* stg = (float*)sm;                         // [128][68]
    #pragma unroll
    for (int j = 0; j < 4; j++)
        wmma::store_matrix_sync(stg + (wid * 16) * 68 + j * 16, acc[j], 68, wmma::mem_row_major);
    __syncthreads();
    #pragma unroll
    for (int s = 0; s < 8; s++) {
        const int slot = tid + s * 256;              // 2048 float4 slots
        const int r = slot >> 4, c4 = (slot & 15) * 4;
        float4 v;
        v.x = stg[r * 68 + c4 + 0]; v.y = stg[r * 68 + c4 + 1];
        v.z = stg[r * 68 + c4 + 2]; v.w = stg[r * 68 + c4 + 3];
        __nv_bfloat16 h[4], l[4];
        split_bf16(v.x, h[0], l[0]); split_bf16(v.y, h[1], l[1]);
        split_bf16(v.z, h[2], l[2]); split_bf16(v.w, h[3], l[3]);
        const size_t base = ((size_t)bb * Ssz + bm * 128 + r) * Dm + hh * DKk + c4;
        *(uint2*)(Oh + base) = *(uint2*)h;
        *(uint2*)(Ol + base) = *(uint2*)l;
    }
}

// ===================== embedding / layernorm (split out) ====================
__global__ __launch_bounds__(256) void embed_k(
    const int* __restrict__ ids, const float* __restrict__ tok,
    const float* __restrict__ pos, float* __restrict__ x)
{
    const int row = blockIdx.x;
    const int s   = row & (Ssz - 1);
    const int id  = ids[row];
    const int t   = threadIdx.x;
    float4 tv = *(const float4*)(tok + (size_t)id * Dm + t * 4);
    float4 pv = *(const float4*)(pos + (size_t)s  * Dm + t * 4);
    float4 o; o.x = tv.x + pv.x; o.y = tv.y + pv.y; o.z = tv.z + pv.z; o.w = tv.w + pv.w;
    *(float4*)(x + (size_t)row * Dm + t * 4) = o;
}

__global__ __launch_bounds__(256) void layernorm_split_k(
    const float* __restrict__ x, const float* __restrict__ g,
    const float* __restrict__ be,
    __nv_bfloat16* __restrict__ oh, __nv_bfloat16* __restrict__ ol)
{
    const int row = blockIdx.x;
    const int t   = threadIdx.x;
    const float* xr = x + (size_t)row * Dm;
    float4 v = *(const float4*)(xr + t * 4);
    float s  = v.x + v.y + v.z + v.w;
    float ss = v.x*v.x + v.y*v.y + v.z*v.z + v.w*v.w;
    #pragma unroll
    for (int off = 16; off; off >>= 1) {
        s  += __shfl_xor_sync(0xffffffffu, s,  off);
        ss += __shfl_xor_sync(0xffffffffu, ss, off);
    }
    __shared__ float rs[8], rss[8];
    const int warp = t >> 5, lane = t & 31;
    if (lane == 0) { rs[warp] = s; rss[warp] = ss; }
    __syncthreads();
    s = 0.f; ss = 0.f;
    #pragma unroll
    for (int i = 0; i < 8; i++) { s += rs[i]; ss += rss[i]; }
    const float mean = s  * (1.0f / Dm);
    const float var  = ss * (1.0f / Dm) - mean * mean;
    const float rstd = rsqrtf(var + 1e-5f);
    float4 gv = *(const float4*)(g  + t * 4);
    float4 bv = *(const float4*)(be + t * 4);
    float o0 = (v.x - mean) * rstd * gv.x + bv.x;
    float o1 = (v.y - mean) * rstd * gv.y + bv.y;
    float o2 = (v.z - mean) * rstd * gv.z + bv.z;
    float o3 = (v.w - mean) * rstd * gv.w + bv.w;
    __nv_bfloat16 h[4], l[4];
    split_bf16(o0, h[0], l[0]); split_bf16(o1, h[1], l[1]);
    split_bf16(o2, h[2], l[2]); split_bf16(o3, h[3], l[3]);
    *(uint2*)(oh + (size_t)row * Dm + t * 4) = *(uint2*)h;
    *(uint2*)(ol + (size_t)row * Dm + t * 4) = *(uint2*)l;
}

// ===================== driver ===============================================
extern "C" void kernel_launch(void* const* d_in, const int* in_sizes, int n_in,
                              void* d_out, int out_size)
{
    const int*   ids  = (const int*)  d_in[0];
    const float* tok  = (const float*)d_in[1];
    const float* pos  = (const float*)d_in[2];
    const float* Wq   = (const float*)d_in[3];
    const float* bq   = (const float*)d_in[4];
    const float* Wk   = (const float*)d_in[5];
    const float* bk   = (const float*)d_in[6];
    const float* Wv   = (const float*)d_in[7];
    const float* bv   = (const float*)d_in[8];
    const float* Wo   = (const float*)d_in[9];
    const float* bo   = (const float*)d_in[10];
    const float* W1   = (const float*)d_in[11];
    const float* b1   = (const float*)d_in[12];
    const float* W2   = (const float*)d_in[13];
    const float* b2   = (const float*)d_in[14];
    const float* ln1g = (const float*)d_in[15];
    const float* ln1b = (const float*)d_in[16];
    const float* ln2g = (const float*)d_in[17];
    const float* ln2b = (const float*)d_in[18];
    const float* lnfg = (const float*)d_in[19];
    const float* lnfb = (const float*)d_in[20];
    const float* Wout = (const float*)d_in[21];
    const float* bout = (const float*)d_in[22];
    float* out = (float*)d_out;

    float *x, *sc;
    __nv_bfloat16 *wc, *hh, *hl, *oh, *ol, *ffh, *ffl;
    __nv_bfloat16 *qh, *ql, *kh, *kl, *vh, *vl, *ph, *pl;
    cudaGetSymbolAddress((void**)&x,  g_x);
    cudaGetSymbolAddress((void**)&sc, g_sc);
    cudaGetSymbolAddress((void**)&wc, g_wc);
    cudaGetSymbolAddress((void**)&hh, g_hh);   cudaGetSymbolAddress((void**)&hl, g_hl);
    cudaGetSymbolAddress((void**)&oh, g_oh);   cudaGetSymbolAddress((void**)&ol, g_ol);
    cudaGetSymbolAddress((void**)&ffh, g_ffh); cudaGetSymbolAddress((void**)&ffl, g_ffl);
    cudaGetSymbolAddress((void**)&qh, g_qh);   cudaGetSymbolAddress((void**)&ql, g_ql);
    cudaGetSymbolAddress((void**)&kh, g_kh);   cudaGetSymbolAddress((void**)&kl, g_kl);
    cudaGetSymbolAddress((void**)&vh, g_vh);   cudaGetSymbolAddress((void**)&vl, g_vl);
    cudaGetSymbolAddress((void**)&ph, g_ph);   cudaGetSymbolAddress((void**)&pl, g_pl);

    cudaFuncSetAttribute(hmma_gemm_k<128, F_BIAS>,                    cudaFuncAttributeMaxDynamicSharedMemorySize, SMEM_B128);
    cudaFuncSetAttribute(hmma_gemm_k<128, F_BIAS|F_QKVOUT>,           cudaFuncAttributeMaxDynamicSharedMemorySize, SMEM_B128);
    cudaFuncSetAttribute(hmma_gemm_k<128, F_BIAS|F_RELU|F_SPLITOUT>,  cudaFuncAttributeMaxDynamicSharedMemorySize, SMEM_B128);
    cudaFuncSetAttribute(hmma_gemm_k<64,  F_BIAS|F_RES>,              cudaFuncAttributeMaxDynamicSharedMemorySize, SMEM_B64);
    cudaFuncSetAttribute(attn_scores_mma, cudaFuncAttributeMaxDynamicSharedMemorySize, SMEM_SCORE);
    cudaFuncSetAttribute(attn_av_mma,     cudaFuncAttributeMaxDynamicSharedMemorySize, SMEM_AV);

    convert_w_k<<<dim3(Dm/32, Dm/32, Ll), 256>>>(Wq,   wc + OFF_Q,  Dm, Dm);
    convert_w_k<<<dim3(Dm/32, Dm/32, Ll), 256>>>(Wk,   wc + OFF_K,  Dm, Dm);
    convert_w_k<<<dim3(Dm/32, Dm/32, Ll), 256>>>(Wv,   wc + OFF_V,  Dm, Dm);
    convert_w_k<<<dim3(Dm/32, Dm/32, Ll), 256>>>(Wo,   wc + OFF_O,  Dm, Dm);
    convert_w_k<<<dim3(Ff/32, Dm/32, Ll), 256>>>(W1,   wc + OFF_W1, Dm, Ff);
    convert_w_k<<<dim3(Dm/32, Ff/32, Ll), 256>>>(W2,   wc + OFF_W2, Ff, Dm);
    convert_w_k<<<dim3(Vv/32, Dm/32, 1),  256>>>(Wout, wc + OFF_WO, Dm, Vv);

    embed_k<<<TOK, 256>>>(ids, tok, pos, x);

    const dim3 gQKV(Dm/128, TOK/128, 3);
    const dim3 gProj64(Dm/64, TOK/128, 1);
    const dim3 gFfn1(Ff/128, TOK/128, 1);
    const dim3 gLogit(Vv/128, TOK/128, 1);
    const dim3 gScore(Ssz/128, Ssz/128, BH);
    const dim3 gAv(Ssz/128, 1, BH);

    for (int l = 0; l < Ll; l++) {
        const size_t oDb = (size_t)l * Dm;
        const size_t oFb = (size_t)l * Ff;
        const size_t oq = (size_t)l * SQW, o1 = (size_t)l * SW1;

        layernorm_split_k<<<TOK, 256>>>(x, ln1g + oDb, ln1b + oDb, hh, hl);

        GemmArgs qa{};
        qa.Ahi = hh; qa.Alo = hl; qa.K = Dm; qa.ldc = Dm;
        qa.Bhi[0] = wc + OFF_Q + oq; qa.Blo[0] = qa.Bhi[0] + (size_t)Dm*Dm;
        qa.Bhi[1] = wc + OFF_K + oq; qa.Blo[1] = qa.Bhi[1] + (size_t)Dm*Dm;
        qa.Bhi[2] = wc + OFF_V + oq; qa.Blo[2] = qa.Bhi[2] + (size_t)Dm*Dm;
        qa.bias[0] = bq + oDb; qa.bias[1] = bk + oDb; qa.bias[2] = bv + oDb;
        qa.Chi[0] = qh; qa.Clo[0] = ql;
        qa.Chi[1] = kh; qa.Clo[1] = kl;
        qa.Chi[2] = vh; qa.Clo[2] = vl;
        hmma_gemm_k<128, F_BIAS|F_QKVOUT><<<gQKV, 256, SMEM_B128>>>(qa);

        attn_scores_mma<<<gScore, 256, SMEM_SCORE>>>(qh, ql, kh, kl, sc);
        softmax_k<<<(BH*Ssz)/8, 256>>>(sc, ph, pl);
        attn_av_mma<<<gAv, 256, SMEM_AV>>>(ph, pl, vh, vl, oh, ol);

        GemmArgs oa{};
        oa.Ahi = oh; oa.Alo = ol; oa.K = Dm; oa.ldc = Dm;
        oa.Bhi[0] = wc + OFF_O + oq; oa.Blo[0] = oa.Bhi[0] + (size_t)Dm*Dm;
        oa.bias[0] = bo + oDb; oa.Res = x; oa.C[0] = x;
        hmma_gemm_k<64, F_BIAS|F_RES><<<gProj64, 256, SMEM_B64>>>(oa);

        layernorm_split_k<<<TOK, 256>>>(x, ln2g + oDb, ln2b + oDb, hh, hl);

        GemmArgs fa{};
        fa.Ahi = hh; fa.Alo = hl; fa.K = Dm; fa.ldc = Ff;
        fa.Bhi[0] = wc + OFF_W1 + o1; fa.Blo[0] = fa.Bhi[0] + (size_t)Dm*Ff;
        fa.bias[0] = b1 + oFb; fa.Chi[0] = ffh; fa.Clo[0] = ffl;
        hmma_gemm_k<128, F_BIAS|F_RELU|F_SPLITOUT><<<gFfn1, 256, SMEM_B128>>>(fa);

        GemmArgs f2{};
        f2.Ahi = ffh; f2.Alo = ffl; f2.K = Ff; f2.ldc = Dm;
        f2.Bhi[0] = wc + OFF_W2 + o1; f2.Blo[0] = f2.Bhi[0] + (size_t)Dm*Ff;
        f2.bias[0] = b2 + oDb; f2.Res = x; f2.C[0] = x;
        hmma_gemm_k<64, F_BIAS|F_RES><<<gProj64, 256, SMEM_B64>>>(f2);
    }

    layernorm_split_k<<<TOK, 256>>>(x, lnfg, lnfb, hh, hl);

    GemmArgs la{};
    la.Ahi = hh; la.Alo = hl; la.K = Dm; la.ldc = Vv;
    la.Bhi[0] = wc + OFF_WO; la.Blo[0] = la.Bhi[0] + (size_t)Dm*Vv;
    la.bias[0] = bout; la.C[0] = out;
    hmma_gemm_k<128, F_BIAS><<<gLogit, 256, SMEM_B128>>>(la);
}

// round 11
// speedup vs baseline: 2.3012x; 1.0136x over previous
#include <cuda_runtime.h>
#include <cuda_bf16.h>
#include <mma.h>
#include <cstdint>
#include <cstddef>

using namespace nvcuda;

#define Bsz 2
#define Ssz 1024
#define Dm  1024
#define Hh  16
#define DKk 64
#define Ff  4096
#define Vv  32000
#define Ll  8
#define TOK (Bsz*Ssz)
#define BH  (Bsz*Hh)

// ===================== scratch ==============================================
__device__ float g_x [TOK*Dm];
__device__ float g_sc[(size_t)BH*Ssz*Ssz];
__device__ __nv_bfloat16 g_hh[TOK*Dm],  g_hl[TOK*Dm];
__device__ __nv_bfloat16 g_oh[TOK*Dm],  g_ol[TOK*Dm];
__device__ __nv_bfloat16 g_ffh[TOK*Ff], g_ffl[TOK*Ff];
__device__ __nv_bfloat16 g_ph[(size_t)BH*Ssz*Ssz];
__device__ __nv_bfloat16 g_pl[(size_t)BH*Ssz*Ssz];
__device__ __nv_bfloat16 g_qh[TOK*Dm], g_ql[TOK*Dm];
__device__ __nv_bfloat16 g_kh[TOK*Dm], g_kl[TOK*Dm];
__device__ __nv_bfloat16 g_vh[TOK*Dm], g_vl[TOK*Dm];

#define SQW ((size_t)2*Dm*Dm)
#define SW1 ((size_t)2*Dm*Ff)
#define OFF_Q  ((size_t)0)
#define OFF_K  (OFF_Q  + (size_t)Ll*SQW)
#define OFF_V  (OFF_K  + (size_t)Ll*SQW)
#define OFF_O  (OFF_V  + (size_t)Ll*SQW)
#define OFF_W1 (OFF_O  + (size_t)Ll*SQW)
#define OFF_W2 (OFF_W1 + (size_t)Ll*SW1)
#define OFF_WO (OFF_W2 + (size_t)Ll*SW1)
#define WC_TOTAL (OFF_WO + (size_t)2*Dm*Vv)
__device__ __nv_bfloat16 g_wc[WC_TOTAL];

__device__ __forceinline__ void split_bf16(float v, __nv_bfloat16& h, __nv_bfloat16& l) {
    h = __float2bfloat16(v);
    l = __float2bfloat16(v - __bfloat162float(h));
}
__device__ __forceinline__ void cpa16(void* s, const void* g) {
    uint32_t sa = (uint32_t)__cvta_generic_to_shared(s);
    asm volatile("cp.async.cg.shared.global [%0], [%1], 16;" :: "r"(sa), "l"(g));
}
#define CP_COMMIT() asm volatile("cp.async.commit_group;" ::: "memory")
#define CP_WAIT1()  asm volatile("cp.async.wait_group 1;" ::: "memory")
#define CP_WAIT0()  asm volatile("cp.async.wait_group 0;" ::: "memory")

__device__ __forceinline__ void ldsm4(uint32_t addr, uint32_t* r) {
    asm volatile("ldmatrix.sync.aligned.m8n8.x4.shared.b16 {%0,%1,%2,%3}, [%4];"
        : "=r"(r[0]), "=r"(r[1]), "=r"(r[2]), "=r"(r[3]) : "r"(addr));
}
__device__ __forceinline__ void mma16816(float* d, const uint32_t* a, const uint32_t* b) {
    asm volatile("mma.sync.aligned.m16n8k16.row.col.f32.bf16.bf16.f32 "
        "{%0,%1,%2,%3}, {%4,%5,%6,%7}, {%8,%9}, {%0,%1,%2,%3};"
        : "+f"(d[0]), "+f"(d[1]), "+f"(d[2]), "+f"(d[3])
        : "r"(a[0]), "r"(a[1]), "r"(a[2]), "r"(a[3]), "r"(b[0]), "r"(b[1]));
}

// ======= weight convert: W [K,N] fp32 -> hi/lo [N,K] bf16 (transpose) =======
__global__ __launch_bounds__(256) void convert_w_k(
    const float* __restrict__ W, __nv_bfloat16* __restrict__ out, int Kd, int Nd)
{
    __shared__ float t[32][33];
    const int l = blockIdx.z;
    const float* Wl = W + (size_t)l * Kd * Nd;
    __nv_bfloat16* hi = out + (size_t)l * 2 * Kd * Nd;
    __nv_bfloat16* lo = hi + (size_t)Kd * Nd;
    const int nb = blockIdx.x * 32, kb = blockIdx.y * 32;
    const int tx = threadIdx.x & 31, ty = threadIdx.x >> 5;
    #pragma unroll
    for (int j = 0; j < 32; j += 8)
        t[ty + j][tx] = Wl[(size_t)(kb + ty + j) * Nd + nb + tx];
    __syncthreads();
    #pragma unroll
    for (int j = 0; j < 32; j += 8) {
        const int n = nb + ty + j, k = kb + tx;
        float v = t[tx][ty + j];
        __nv_bfloat16 h, l2; split_bf16(v, h, l2);
        hi[(size_t)n * Kd + k] = h;
        lo[(size_t)n * Kd + k] = l2;
    }
}

// ===================== GEMM v4: raw mma.sync, 3-stage cp.async ==============
#define F_BIAS 1
#define F_RES  2
#define F_RELU 4
#define F_QKVOUT 8
#define F_SPLITOUT 16

struct GemmArgs {
    const __nv_bfloat16 *Ahi, *Alo;
    const __nv_bfloat16 *Bhi[3], *Blo[3];
    const float* bias[3];
    const float* Res;
    float* C[3];
    __nv_bfloat16 *Chi[3], *Clo[3];
    int K;
    int ldc;
};

// layout per stage buffer (bytes): Ah[128][40] Al Bh[128][40] Bl ; PITB=80
#define PITB 80
#define AH_OFF 0
#define AL_OFF (128*PITB)
#define BH_OFF (2*128*PITB)
#define BL_OFF (3*128*PITB)
#define STGB   (4*128*PITB)            // 40960 bytes per stage
#define SMEM_GM (3*STGB)               // 122880

template<int FLAGS>
__global__ __launch_bounds__(256) void mma_gemm_k(GemmArgs ga)
{
    constexpr int BM = 128, BN = 128, BK = 32;
    extern __shared__ __nv_bfloat16 smb[];
    char* smc = (char*)smb;

    const int tid = threadIdx.x, wid = tid >> 5, lane = tid & 31;
    const int z = blockIdx.z;
    const int Kd = ga.K;
    const __nv_bfloat16* Ah = ga.Ahi + (size_t)blockIdx.y * BM * Kd;
    const __nv_bfloat16* Al = ga.Alo + (size_t)blockIdx.y * BM * Kd;
    const __nv_bfloat16* Bh = ga.Bhi[z] + (size_t)blockIdx.x * BN * Kd;
    const __nv_bfloat16* Bl = ga.Blo[z] + (size_t)blockIdx.x * BN * Kd;
    const int wm = wid & 3, wn = wid >> 2;     // warp tile 32 x 64

    auto stage_load = [&](int buf, int k0) {
        char* s = smc + buf * STGB;
        #pragma unroll
        for (int ss = 0; ss < 2; ss++) {
            const int slot = tid + ss * 256;
            const int r = slot >> 2, c = slot & 3;
            cpa16(s + AH_OFF + r * PITB + c * 16, Ah + (size_t)r * Kd + k0 + c * 8);
            cpa16(s + AL_OFF + r * PITB + c * 16, Al + (size_t)r * Kd + k0 + c * 8);
        }
        #pragma unroll
        for (int ss = 0; ss < 2; ss++) {
            const int slot = tid + ss * 256;
            const int r = slot >> 2, c = slot & 3;
            cpa16(s + BH_OFF + r * PITB + c * 16, Bh + (size_t)r * Kd + k0 + c * 8);
            cpa16(s + BL_OFF + r * PITB + c * 16, Bl + (size_t)r * Kd + k0 + c * 8);
        }
        CP_COMMIT();
    };

    // precomputed ldmatrix byte offsets (per lane) within a stage buffer
    // A (x4 -> a0..a3 of m16k16): rows wm*32+ii*16+(lane&15), col +((lane>>4)&1)*16
    uint32_t offA[2];
    #pragma unroll
    for (int ii = 0; ii < 2; ii++)
        offA[ii] = (uint32_t)((wm * 32 + ii * 16 + (lane & 15)) * PITB + ((lane >> 4) & 1) * 16);
    // B (x4 -> frags 2jj,2jj+1): rows wn*64+jj*16+(lane&7)+((lane>>4)&1)*8, col +((lane>>3)&1)*16
    uint32_t offB[4];
    #pragma unroll
    for (int jj = 0; jj < 4; jj++)
        offB[jj] = (uint32_t)((wn * 64 + jj * 16 + (lane & 7) + ((lane >> 4) & 1) * 8) * PITB
                              + ((lane >> 3) & 1) * 16);

    const uint32_t smem_u32 = (uint32_t)__cvta_generic_to_shared(smc);

    float acc[2][8][4];
    #pragma unroll
    for (int i = 0; i < 2; i++)
        #pragma unroll
        for (int j = 0; j < 8; j++)
            #pragma unroll
            for (int e = 0; e < 4; e++) acc[i][j][e] = 0.f;

    const int nst = Kd / BK;
    stage_load(0, 0);
    stage_load(1, BK);
    for (int i = 0; i < nst; i++) {
        if (i + 1 < nst) { CP_WAIT1(); } else { CP_WAIT0(); }
        __syncthreads();
        if (i + 2 < nst) stage_load((i + 2) % 3, (i + 2) * BK);
        const uint32_t sb = smem_u32 + (uint32_t)((i % 3) * STGB);
        #pragma unroll
        for (int kk = 0; kk < BK; kk += 16) {
            const uint32_t kb = sb + kk * 2;
            uint32_t ah[2][4], al[2][4], bh[16], bl[16];
            #pragma unroll
            for (int ii = 0; ii < 2; ii++) {
                ldsm4(kb + AH_OFF + offA[ii], ah[ii]);
                ldsm4(kb + AL_OFF + offA[ii], al[ii]);
            }
            #pragma unroll
            for (int jj = 0; jj < 4; jj++) {
                ldsm4(kb + BH_OFF + offB[jj], bh + jj * 4);
                ldsm4(kb + BL_OFF + offB[jj], bl + jj * 4);
            }
            #pragma unroll
            for (int ii = 0; ii < 2; ii++)
                #pragma unroll
                for (int j = 0; j < 8; j++) mma16816(acc[ii][j], ah[ii], bh + j * 2);
            #pragma unroll
            for (int ii = 0; ii < 2; ii++)
                #pragma unroll
                for (int j = 0; j < 8; j++) mma16816(acc[ii][j], ah[ii], bl + j * 2);
            #pragma unroll
            for (int ii = 0; ii < 2; ii++)
                #pragma unroll
                for (int j = 0; j < 8; j++) mma16816(acc[ii][j], al[ii], bh + j * 2);
        }
        __syncthreads();
    }

    // epilogue: acc -> SMEM staging -> writeout
    constexpr int SP = BN + 4;
    float* st = (float*)smb;
    const int er = lane >> 2, ec = (lane & 3) * 2;
    #pragma unroll
    for (int ii = 0; ii < 2; ii++)
        #pragma unroll
        for (int j = 0; j < 8; j++) {
            const int r0 = wm * 32 + ii * 16 + er;
            const int c0 = wn * 64 + j * 8 + ec;
            st[r0 * SP + c0]       = acc[ii][j][0];
            st[r0 * SP + c0 + 1]   = acc[ii][j][1];
            st[(r0+8) * SP + c0]     = acc[ii][j][2];
            st[(r0+8) * SP + c0 + 1] = acc[ii][j][3];
        }
    __syncthreads();

    const float* bias = ga.bias[z] + (size_t)blockIdx.x * BN;
    #pragma unroll
    for (int jj = 0; jj < 16; jj++) {
        const int idx = tid + jj * 256;
        const int r = idx >> 5, c4 = (idx & 31) * 4;
        float4 v;
        v.x = st[r * SP + c4 + 0]; v.y = st[r * SP + c4 + 1];
        v.z = st[r * SP + c4 + 2]; v.w = st[r * SP + c4 + 3];
        if (FLAGS & F_BIAS) {
            float4 b4 = *(const float4*)(bias + c4);
            v.x += b4.x; v.y += b4.y; v.z += b4.z; v.w += b4.w;
        }
        if (FLAGS & F_RELU) {
            v.x = fmaxf(v.x, 0.f); v.y = fmaxf(v.y, 0.f);
            v.z = fmaxf(v.z, 0.f); v.w = fmaxf(v.w, 0.f);
        }
        if (FLAGS & F_QKVOUT) {
            const int token = blockIdx.y * BM + r;
            const int bb = token >> 10, ss = token & 1023;
            const int f = blockIdx.x * BN + c4;
            const int hh2 = f >> 6, dk = f & 63;
            const size_t base = (((size_t)bb * Hh + hh2) * Ssz + ss) * DKk + dk;
            __nv_bfloat16 h[4], l[4];
            split_bf16(v.x, h[0], l[0]); split_bf16(v.y, h[1], l[1]);
            split_bf16(v.z, h[2], l[2]); split_bf16(v.w, h[3], l[3]);
            *(uint2*)(ga.Chi[z] + base) = *(uint2*)h;
            *(uint2*)(ga.Clo[z] + base) = *(uint2*)l;
        } else if (FLAGS & F_SPLITOUT) {
            const size_t base = (size_t)(blockIdx.y * BM + r) * ga.ldc + blockIdx.x * BN + c4;
            __nv_bfloat16 h[4], l[4];
            split_bf16(v.x, h[0], l[0]); split_bf16(v.y, h[1], l[1]);
            split_bf16(v.z, h[2], l[2]); split_bf16(v.w, h[3], l[3]);
            *(uint2*)(ga.Chi[z] + base) = *(uint2*)h;
            *(uint2*)(ga.Clo[z] + base) = *(uint2*)l;
        } else {
            if (FLAGS & F_RES) {
                const float* R = ga.Res + (size_t)blockIdx.y * BM * ga.ldc + (size_t)blockIdx.x * BN;
                float4 r4 = *(const float4*)(R + (size_t)r * ga.ldc + c4);
                v.x += r4.x; v.y += r4.y; v.z += r4.z; v.w += r4.w;
            }
            float* C = ga.C[z] + (size_t)blockIdx.y * BM * ga.ldc + (size_t)blockIdx.x * BN;
            *(float4*)(C + (size_t)r * ga.ldc + c4) = v;
        }
    }
}

// ===================== attention: scores via HMMA (wmma) ====================
#define APIT 72
#define SMEM_SCORE (4 * 128 * APIT * 2)

__global__ __launch_bounds__(256) void attn_scores_mma(
    const __nv_bfloat16* __restrict__ Qh, const __nv_bfloat16* __restrict__ Ql,
    const __nv_bfloat16* __restrict__ Kh, const __nv_bfloat16* __restrict__ Kl,
    float* __restrict__ Sc)
{
    const int bm = blockIdx.y, bn = blockIdx.x;
    if (bn > bm) return;
    const int bh = blockIdx.z;
    extern __shared__ char sm[];
    __nv_bfloat16* sQh = (__nv_bfloat16*)sm;
    __nv_bfloat16* sQl = sQh + 128 * APIT;
    __nv_bfloat16* sKh = sQl + 128 * APIT;
    __nv_bfloat16* sKl = sKh + 128 * APIT;

    const int tid = threadIdx.x, wid = tid >> 5;
    const size_t qoff = ((size_t)bh * Ssz + bm * 128) * DKk;
    const size_t koff = ((size_t)bh * Ssz + bn * 128) * DKk;
    #pragma unroll
    for (int s = 0; s < 4; s++) {
        const int slot = tid + s * 256;
        const int r = slot >> 3, c8 = slot & 7;
        *(uint4*)&sQh[r * APIT + c8 * 8] = *(const uint4*)(Qh + qoff + (size_t)r * DKk + c8 * 8);
        *(uint4*)&sQl[r * APIT + c8 * 8] = *(const uint4*)(Ql + qoff + (size_t)r * DKk + c8 * 8);
        *(uint4*)&sKh[r * APIT + c8 * 8] = *(const uint4*)(Kh + koff + (size_t)r * DKk + c8 * 8);
        *(uint4*)&sKl[r * APIT + c8 * 8] = *(const uint4*)(Kl + koff + (size_t)r * DKk + c8 * 8);
    }
    __syncthreads();

    const int wm = wid & 3, wn = wid >> 2;
    wmma::fragment<wmma::accumulator, 16, 16, 16, float> acc[2][4];
    #pragma unroll
    for (int i = 0; i < 2; i++)
        #pragma unroll
        for (int j = 0; j < 4; j++) wmma::fill_fragment(acc[i][j], 0.0f);

    #pragma unroll
    for (int kk = 0; kk < 64; kk += 16) {
        wmma::fragment<wmma::matrix_a, 16, 16, 16, __nv_bfloat16, wmma::row_major> fah[2], fal[2];
        wmma::fragment<wmma::matrix_b, 16, 16, 16, __nv_bfloat16, wmma::col_major> fbh[4], fbl[4];
        #pragma unroll
        for (int ii = 0; ii < 2; ii++) {
            wmma::load_matrix_sync(fah[ii], sQh + (wm * 32 + ii * 16) * APIT + kk, APIT);
            wmma::load_matrix_sync(fal[ii], sQl + (wm * 32 + ii * 16) * APIT + kk, APIT);
        }
        #pragma unroll
        for (int j = 0; j < 4; j++) {
            wmma::load_matrix_sync(fbh[j], sKh + (wn * 64 + j * 16) * APIT + kk, APIT);
            wmma::load_matrix_sync(fbl[j], sKl + (wn * 64 + j * 16) * APIT + kk, APIT);
        }
        #pragma unroll
        for (int ii = 0; ii < 2; ii++)
            #pragma unroll
            for (int j = 0; j < 4; j++) {
                wmma::mma_sync(acc[ii][j], fah[ii], fbh[j], acc[ii][j]);
                wmma::mma_sync(acc[ii][j], fah[ii], fbl[j], acc[ii][j]);
                wmma::mma_sync(acc[ii][j], fal[ii], fbh[j], acc[ii][j]);
            }
    }
    float* Cb = Sc + (size_t)bh * Ssz * Ssz + (size_t)(bm * 128) * Ssz + bn * 128;
    #pragma unroll
    for (int ii = 0; ii < 2; ii++)
        #pragma unroll
        for (int j = 0; j < 4; j++) {
            #pragma unroll
            for (int t = 0; t < acc[ii][j].num_elements; t++) acc[ii][j].x[t] *= 0.125f;
            wmma::store_matrix_sync(Cb + (size_t)(wm * 32 + ii * 16) * Ssz + wn * 64 + j * 16,
                                    acc[ii][j], Ssz, wmma::mem_row_major);
        }
}

// ===================== softmax: fp32 in -> bf16 hi/lo probs =================
__global__ __launch_bounds__(256) void softmax_k(
    const float* __restrict__ Sc, __nv_bfloat16* __restrict__ Ph,
    __nv_bfloat16* __restrict__ Pl)
{
    const int warp = threadIdx.x >> 5, lane = threadIdx.x & 31;
    const int row = blockIdx.x * 8 + warp;
    const int bh = row >> 10, q = row & 1023;
    const float* r = Sc + (size_t)bh * Ssz * Ssz + (size_t)q * Ssz;
    const int n = q + 1;
    float vals[32];
    float m = -3.0e38f;
    #pragma unroll
    for (int i = 0; i < 32; i++) {
        const int k = lane + i * 32;
        float v = (k < n) ? r[k] : -3.0e38f;
        vals[i] = v; m = fmaxf(m, v);
    }
    #pragma unroll
    for (int off = 16; off; off >>= 1) m = fmaxf(m, __shfl_xor_sync(0xffffffffu, m, off));
    float s = 0.f;
    #pragma unroll
    for (int i = 0; i < 32; i++) { float e = __expf(vals[i] - m); vals[i] = e; s += e; }
    #pragma unroll
    for (int off = 16; off; off >>= 1) s += __shfl_xor_sync(0xffffffffu, s, off);
    const float inv = 1.0f / s;
    const int kend = ((q >> 7) + 1) << 7;
    __nv_bfloat16* ph = Ph + (size_t)bh * Ssz * Ssz + (size_t)q * Ssz;
    __nv_bfloat16* pl = Pl + (size_t)bh * Ssz * Ssz + (size_t)q * Ssz;
    #pragma unroll
    for (int i = 0; i < 32; i++) {
        const int k = lane + i * 32;
        if (k < kend) {
            float p = (k < n) ? vals[i] * inv : 0.f;
            __nv_bfloat16 h, l; split_bf16(p, h, l);
            ph[k] = h; pl[k] = l;
        }
    }
}

// ===================== O = P @ V via HMMA (split output) ====================
#define SMEM_AV ((128 * APIT * 2 + 64 * APIT * 2) * 2)

__global__ __launch_bounds__(256) void attn_av_mma(
    const __nv_bfloat16* __restrict__ Ph, const __nv_bfloat16* __restrict__ Pl,
    const __nv_bfloat16* __restrict__ Vh, const __nv_bfloat16* __restrict__ Vl,
    __nv_bfloat16* __restrict__ Oh, __nv_bfloat16* __restrict__ Ol)
{
    const int bh = blockIdx.z, bb = bh >> 4, hh = bh & 15;
    const int bm = blockIdx.x;
    extern __shared__ char sm[];
    __nv_bfloat16* sPh = (__nv_bfloat16*)sm;
    __nv_bfloat16* sPl = sPh + 128 * APIT;
    __nv_bfloat16* sVh = sPl + 128 * APIT;
    __nv_bfloat16* sVl = sVh + 64 * APIT;

    const int tid = threadIdx.x, wid = tid >> 5;
    const __nv_bfloat16* Pbh = Ph + (size_t)bh * Ssz * Ssz + (size_t)(bm * 128) * Ssz;
    const __nv_bfloat16* Pbl = Pl + (size_t)bh * Ssz * Ssz + (size_t)(bm * 128) * Ssz;
    const __nv_bfloat16* Vbh = Vh + (size_t)bh * Ssz * DKk;
    const __nv_bfloat16* Vbl = Vl + (size_t)bh * Ssz * DKk;

    wmma::fragment<wmma::accumulator, 16, 16, 16, float> acc[4];
    #pragma unroll
    for (int j = 0; j < 4; j++) wmma::fill_fragment(acc[j], 0.0f);

    const int Kmax = (bm + 1) * 128;
    for (int k0 = 0; k0 < Kmax; k0 += 64) {
        #pragma unroll
        for (int s = 0; s < 4; s++) {
            const int slot = tid + s * 256;
            const int r = slot >> 3, c8 = slot & 7;
            *(uint4*)&sPh[r * APIT + c8 * 8] = *(const uint4*)(Pbh + (size_t)r * Ssz + k0 + c8 * 8);
            *(uint4*)&sPl[r * APIT + c8 * 8] = *(const uint4*)(Pbl + (size_t)r * Ssz + k0 + c8 * 8);
        }
        #pragma unroll
        for (int s = 0; s < 2; s++) {
            const int slot = tid + s * 256;
            const int r = slot >> 3, c8 = slot & 7;
            *(uint4*)&sVh[r * APIT + c8 * 8] = *(const uint4*)(Vbh + (size_t)(k0 + r) * DKk + c8 * 8);
            *(uint4*)&sVl[r * APIT + c8 * 8] = *(const uint4*)(Vbl + (size_t)(k0 + r) * DKk + c8 * 8);
        }
        __syncthreads();
        #pragma unroll
        for (int kk = 0; kk < 64; kk += 16) {
            wmma::fragment<wmma::matrix_a, 16, 16, 16, __nv_bfloat16, wmma::row_major> fah, fal;
            wmma::fragment<wmma::matrix_b, 16, 16, 16, __nv_bfloat16, wmma::row_major> fbh[4], fbl[4];
            wmma::load_matrix_sync(fah, sPh + (wid * 16) * APIT + kk, APIT);
            wmma::load_matrix_sync(fal, sPl + (wid * 16) * APIT + kk, APIT);
            #pragma unroll
            for (int j = 0; j < 4; j++) {
                wmma::load_matrix_sync(fbh[j], sVh + kk * APIT + j * 16, APIT);
                wmma::load_matrix_sync(fbl[j], sVl + kk * APIT + j * 16, APIT);
            }
            #pragma unroll
            for (int j = 0; j < 4; j++) {
                wmma::mma_sync(acc[j], fah, fbh[j], acc[j]);
                wmma::mma_sync(acc[j], fah, fbl[j], acc[j]);
                wmma::mma_sync(acc[j], fal, fbh[j], acc[j]);
            }
        }
        __syncthreads();
    }
    float* stg = (float*)sm;
    #pragma unroll
    for (int j = 0; j < 4; j++)
        wmma::store_matrix_sync(stg + (wid * 16) * 68 + j * 16, acc[j], 68, wmma::mem_row_major);
    __syncthreads();
    #pragma unroll
    for (int s = 0; s < 8; s++) {
        const int slot = tid + s * 256;
        const int r = slot >> 4, c4 = (slot & 15) * 4;
        float4 v;
        v.x = stg[r * 68 + c4 + 0]; v.y = stg[r * 68 + c4 + 1];
        v.z = stg[r * 68 + c4 + 2]; v.w = stg[r * 68 + c4 + 3];
        __nv_bfloat16 h[4], l[4];
        split_bf16(v.x, h[0], l[0]); split_bf16(v.y, h[1], l[1]);
        split_bf16(v.z, h[2], l[2]); split_bf16(v.w, h[3], l[3]);
        const size_t base = ((size_t)bb * Ssz + bm * 128 + r) * Dm + hh * DKk + c4;
        *(uint2*)(Oh + base) = *(uint2*)h;
        *(uint2*)(Ol + base) = *(uint2*)l;
    }
}

// ===================== embedding / layernorm (split out) ====================
__global__ __launch_bounds__(256) void embed_k(
    const int* __restrict__ ids, const float* __restrict__ tok,
    const float* __restrict__ pos, float* __restrict__ x)
{
    const int row = blockIdx.x;
    const int s   = row & (Ssz - 1);
    const int id  = ids[row];
    const int t   = threadIdx.x;
    float4 tv = *(const float4*)(tok + (size_t)id * Dm + t * 4);
    float4 pv = *(const float4*)(pos + (size_t)s  * Dm + t * 4);
    float4 o; o.x = tv.x + pv.x; o.y = tv.y + pv.y; o.z = tv.z + pv.z; o.w = tv.w + pv.w;
    *(float4*)(x + (size_t)row * Dm + t * 4) = o;
}

__global__ __launch_bounds__(256) void layernorm_split_k(
    const float* __restrict__ x, const float* __restrict__ g,
    const float* __restrict__ be,
    __nv_bfloat16* __restrict__ oh, __nv_bfloat16* __restrict__ ol)
{
    const int row = blockIdx.x;
    const int t   = threadIdx.x;
    const float* xr = x + (size_t)row * Dm;
    float4 v = *(const float4*)(xr + t * 4);
    float s  = v.x + v.y + v.z + v.w;
    float ss = v.x*v.x + v.y*v.y + v.z*v.z + v.w*v.w;
    #pragma unroll
    for (int off = 16; off; off >>= 1) {
        s  += __shfl_xor_sync(0xffffffffu, s,  off);
        ss += __shfl_xor_sync(0xffffffffu, ss, off);
    }
    __shared__ float rs[8], rss[8];
    const int warp = t >> 5, lane = t & 31;
    if (lane == 0) { rs[warp] = s; rss[warp] = ss; }
    __syncthreads();
    s = 0.f; ss = 0.f;
    #pragma unroll
    for (int i = 0; i < 8; i++) { s += rs[i]; ss += rss[i]; }
    const float mean = s  * (1.0f / Dm);
    const float var  = ss * (1.0f / Dm) - mean * mean;
    const float rstd = rsqrtf(var + 1e-5f);
    float4 gv = *(const float4*)(g  + t * 4);
    float4 bv = *(const float4*)(be + t * 4);
    float o0 = (v.x - mean) * rstd * gv.x + bv.x;
    float o1 = (v.y - mean) * rstd * gv.y + bv.y;
    float o2 = (v.z - mean) * rstd * gv.z + bv.z;
    float o3 = (v.w - mean) * rstd * gv.w + bv.w;
    __nv_bfloat16 h[4], l[4];
    split_bf16(o0, h[0], l[0]); split_bf16(o1, h[1], l[1]);
    split_bf16(o2, h[2], l[2]); split_bf16(o3, h[3], l[3]);
    *(uint2*)(oh + (size_t)row * Dm + t * 4) = *(uint2*)h;
    *(uint2*)(ol + (size_t)row * Dm + t * 4) = *(uint2*)l;
}

// ===================== driver ===============================================
extern "C" void kernel_launch(void* const* d_in, const int* in_sizes, int n_in,
                              void* d_out, int out_size)
{
    const int*   ids  = (const int*)  d_in[0];
    const float* tok  = (const float*)d_in[1];
    const float* pos  = (const float*)d_in[2];
    const float* Wq   = (const float*)d_in[3];
    const float* bq   = (const float*)d_in[4];
    const float* Wk   = (const float*)d_in[5];
    const float* bk   = (const float*)d_in[6];
    const float* Wv   = (const float*)d_in[7];
    const float* bv   = (const float*)d_in[8];
    const float* Wo   = (const float*)d_in[9];
    const float* bo   = (const float*)d_in[10];
    const float* W1   = (const float*)d_in[11];
    const float* b1   = (const float*)d_in[12];
    const float* W2   = (const float*)d_in[13];
    const float* b2   = (const float*)d_in[14];
    const float* ln1g = (const float*)d_in[15];
    const float* ln1b = (const float*)d_in[16];
    const float* ln2g = (const float*)d_in[17];
    const float* ln2b = (const float*)d_in[18];
    const float* lnfg = (const float*)d_in[19];
    const float* lnfb = (const float*)d_in[20];
    const float* Wout = (const float*)d_in[21];
    const float* bout = (const float*)d_in[22];
    float* out = (float*)d_out;

    float *x, *sc;
    __nv_bfloat16 *wc, *hh, *hl, *oh, *ol, *ffh, *ffl;
    __nv_bfloat16 *qh, *ql, *kh, *kl, *vh, *vl, *ph, *pl;
    cudaGetSymbolAddress((void**)&x,  g_x);
    cudaGetSymbolAddress((void**)&sc, g_sc);
    cudaGetSymbolAddress((void**)&wc, g_wc);
    cudaGetSymbolAddress((void**)&hh, g_hh);   cudaGetSymbolAddress((void**)&hl, g_hl);
    cudaGetSymbolAddress((void**)&oh, g_oh);   cudaGetSymbolAddress((void**)&ol, g_ol);
    cudaGetSymbolAddress((void**)&ffh, g_ffh); cudaGetSymbolAddress((void**)&ffl, g_ffl);
    cudaGetSymbolAddress((void**)&qh, g_qh);   cudaGetSymbolAddress((void**)&ql, g_ql);
    cudaGetSymbolAddress((void**)&kh, g_kh);   cudaGetSymbolAddress((void**)&kl, g_kl);
    cudaGetSymbolAddress((void**)&vh, g_vh);   cudaGetSymbolAddress((void**)&vl, g_vl);
    cudaGetSymbolAddress((void**)&ph, g_ph);   cudaGetSymbolAddress((void**)&pl, g_pl);

    cudaFuncSetAttribute(mma_gemm_k<F_BIAS>,                   cudaFuncAttributeMaxDynamicSharedMemorySize, SMEM_GM);
    cudaFuncSetAttribute(mma_gemm_k<F_BIAS|F_QKVOUT>,          cudaFuncAttributeMaxDynamicSharedMemorySize, SMEM_GM);
    cudaFuncSetAttribute(mma_gemm_k<F_BIAS|F_RELU|F_SPLITOUT>, cudaFuncAttributeMaxDynamicSharedMemorySize, SMEM_GM);
    cudaFuncSetAttribute(mma_gemm_k<F_BIAS|F_RES>,             cudaFuncAttributeMaxDynamicSharedMemorySize, SMEM_GM);
    cudaFuncSetAttribute(attn_scores_mma, cudaFuncAttributeMaxDynamicSharedMemorySize, SMEM_SCORE);
    cudaFuncSetAttribute(attn_av_mma,     cudaFuncAttributeMaxDynamicSharedMemorySize, SMEM_AV);

    convert_w_k<<<dim3(Dm/32, Dm/32, Ll), 256>>>(Wq,   wc + OFF_Q,  Dm, Dm);
    convert_w_k<<<dim3(Dm/32, Dm/32, Ll), 256>>>(Wk,   wc + OFF_K,  Dm, Dm);
    convert_w_k<<<dim3(Dm/32, Dm/32, Ll), 256>>>(Wv,   wc + OFF_V,  Dm, Dm);
    convert_w_k<<<dim3(Dm/32, Dm/32, Ll), 256>>>(Wo,   wc + OFF_O,  Dm, Dm);
    convert_w_k<<<dim3(Ff/32, Dm/32, Ll), 256>>>(W1,   wc + OFF_W1, Dm, Ff);
    convert_w_k<<<dim3(Dm/32, Ff/32, Ll), 256>>>(W2,   wc + OFF_W2, Ff, Dm);
    convert_w_k<<<dim3(Vv/32, Dm/32, 1),  256>>>(Wout, wc + OFF_WO, Dm, Vv);

    embed_k<<<TOK, 256>>>(ids, tok, pos, x);

    const dim3 gQKV(Dm/128, TOK/128, 3);
    const dim3 gProj(Dm/128, TOK/128, 1);
    const dim3 gFfn1(Ff/128, TOK/128, 1);
    const dim3 gLogit(Vv/128, TOK/128, 1);
    const dim3 gScore(Ssz/128, Ssz/128, BH);
    const dim3 gAv(Ssz/128, 1, BH);

    for (int l = 0; l < Ll; l++) {
        const size_t oDb = (size_t)l * Dm;
        const size_t oFb = (size_t)l * Ff;
        const size_t oq = (size_t)l * SQW, o1 = (size_t)l * SW1;

        layernorm_split_k<<<TOK, 256>>>(x, ln1g + oDb, ln1b + oDb, hh, hl);

        GemmArgs qa{};
        qa.Ahi = hh; qa.Alo = hl; qa.K = Dm; qa.ldc = Dm;
        qa.Bhi[0] = wc + OFF_Q + oq; qa.Blo[0] = qa.Bhi[0] + (size_t)Dm*Dm;
        qa.Bhi[1] = wc + OFF_K + oq; qa.Blo[1] = qa.Bhi[1] + (size_t)Dm*Dm;
        qa.Bhi[2] = wc + OFF_V + oq; qa.Blo[2] = qa.Bhi[2] + (size_t)Dm*Dm;
        qa.bias[0] = bq + oDb; qa.bias[1] = bk + oDb; qa.bias[2] = bv + oDb;
        qa.Chi[0] = qh; qa.Clo[0] = ql;
        qa.Chi[1] = kh; qa.Clo[1] = kl;
        qa.Chi[2] = vh; qa.Clo[2] = vl;
        mma_gemm_k<F_BIAS|F_QKVOUT><<<gQKV, 256, SMEM_GM>>>(qa);

        attn_scores_mma<<<gScore, 256, SMEM_SCORE>>>(qh, ql, kh, kl, sc);
        softmax_k<<<(BH*Ssz)/8, 256>>>(sc, ph, pl);
        attn_av_mma<<<gAv, 256, SMEM_AV>>>(ph, pl, vh, vl, oh, ol);

        GemmArgs oa{};
        oa.Ahi = oh; oa.Alo = ol; oa.K = Dm; oa.ldc = Dm;
        oa.Bhi[0] = wc + OFF_O + oq; oa.Blo[0] = oa.Bhi[0] + (size_t)Dm*Dm;
        oa.bias[0] = bo + oDb; oa.Res = x; oa.C[0] = x;
        mma_gemm_k<F_BIAS|F_RES><<<gProj, 256, SMEM_GM>>>(oa);

        layernorm_split_k<<<TOK, 256>>>(x, ln2g + oDb, ln2b + oDb, hh, hl);

        GemmArgs fa{};
        fa.Ahi = hh; fa.Alo = hl; fa.K = Dm; fa.ldc = Ff;
        fa.Bhi[0] = wc + OFF_W1 + o1; fa.Blo[0] = fa.Bhi[0] + (size_t)Dm*Ff;
        fa.bias[0] = b1 + oFb; fa.Chi[0] = ffh; fa.Clo[0] = ffl;
        mma_gemm_k<F_BIAS|F_RELU|F_SPLITOUT><<<gFfn1, 256, SMEM_GM>>>(fa);

        GemmArgs f2{};
        f2.Ahi = ffh; f2.Alo = ffl; f2.K = Ff; f2.ldc = Dm;
        f2.Bhi[0] = wc + OFF_W2 + o1; f2.Blo[0] = f2.Bhi[0] + (size_t)Dm*Ff;
        f2.bias[0] = b2 + oDb; f2.Res = x; f2.C[0] = x;
        mma_gemm_k<F_BIAS|F_RES><<<gProj, 256, SMEM_GM>>>(f2);
    }

    layernorm_split_k<<<TOK, 256>>>(x, lnfg, lnfb, hh, hl);

    GemmArgs la{};
    la.Ahi = hh; la.Alo = hl; la.K = Dm; la.ldc = Vv;
    la.Bhi[0] = wc + OFF_WO; la.Blo[0] = la.Bhi[0] + (size_t)Dm*Vv;
    la.bias[0] = bout; la.C[0] = out;
    mma_gemm_k<F_BIAS><<<gLogit, 256, SMEM_GM>>>(la);
}

// round 12
// speedup vs baseline: 2.3879x; 1.0377x over previous
#include <cuda_runtime.h>
#include <cuda_bf16.h>
#include <mma.h>
#include <cstdint>
#include <cstddef>

using namespace nvcuda;

#define Bsz 2
#define Ssz 1024
#define Dm  1024
#define Hh  16
#define DKk 64
#define Ff  4096
#define Vv  32000
#define Ll  8
#define TOK (Bsz*Ssz)
#define BH  (Bsz*Hh)

// ===================== scratch ==============================================
__device__ float g_x [TOK*Dm];
__device__ float g_sc[(size_t)BH*Ssz*Ssz];
__device__ __nv_bfloat16 g_hh[TOK*Dm],  g_hl[TOK*Dm];
__device__ __nv_bfloat16 g_oh[TOK*Dm],  g_ol[TOK*Dm];
__device__ __nv_bfloat16 g_ffh[TOK*Ff], g_ffl[TOK*Ff];
__device__ __nv_bfloat16 g_ph[(size_t)BH*Ssz*Ssz];
__device__ __nv_bfloat16 g_pl[(size_t)BH*Ssz*Ssz];
__device__ __nv_bfloat16 g_qh[TOK*Dm], g_ql[TOK*Dm];
__device__ __nv_bfloat16 g_kh[TOK*Dm], g_kl[TOK*Dm];
__device__ __nv_bfloat16 g_vh[TOK*Dm], g_vl[TOK*Dm];

#define SQW ((size_t)2*Dm*Dm)
#define SW1 ((size_t)2*Dm*Ff)
#define OFF_Q  ((size_t)0)
#define OFF_K  (OFF_Q  + (size_t)Ll*SQW)
#define OFF_V  (OFF_K  + (size_t)Ll*SQW)
#define OFF_O  (OFF_V  + (size_t)Ll*SQW)
#define OFF_W1 (OFF_O  + (size_t)Ll*SQW)
#define OFF_W2 (OFF_W1 + (size_t)Ll*SW1)
#define OFF_WO (OFF_W2 + (size_t)Ll*SW1)
#define WC_TOTAL (OFF_WO + (size_t)2*Dm*Vv)
__device__ __nv_bfloat16 g_wc[WC_TOTAL];

__device__ __forceinline__ void split_bf16(float v, __nv_bfloat16& h, __nv_bfloat16& l) {
    h = __float2bfloat16(v);
    l = __float2bfloat16(v - __bfloat162float(h));
}
__device__ __forceinline__ void cpa16(void* s, const void* g) {
    uint32_t sa = (uint32_t)__cvta_generic_to_shared(s);
    asm volatile("cp.async.cg.shared.global [%0], [%1], 16;" :: "r"(sa), "l"(g));
}
#define CP_COMMIT() asm volatile("cp.async.commit_group;" ::: "memory")
#define CP_WAIT1()  asm volatile("cp.async.wait_group 1;" ::: "memory")
#define CP_WAIT0()  asm volatile("cp.async.wait_group 0;" ::: "memory")

__device__ __forceinline__ void ldsm4(uint32_t addr, uint32_t* r) {
    asm volatile("ldmatrix.sync.aligned.m8n8.x4.shared.b16 {%0,%1,%2,%3}, [%4];"
        : "=r"(r[0]), "=r"(r[1]), "=r"(r[2]), "=r"(r[3]) : "r"(addr));
}
__device__ __forceinline__ void mma16816(float* d, const uint32_t* a, const uint32_t* b) {
    asm volatile("mma.sync.aligned.m16n8k16.row.col.f32.bf16.bf16.f32 "
        "{%0,%1,%2,%3}, {%4,%5,%6,%7}, {%8,%9}, {%0,%1,%2,%3};"
        : "+f"(d[0]), "+f"(d[1]), "+f"(d[2]), "+f"(d[3])
        : "r"(a[0]), "r"(a[1]), "r"(a[2]), "r"(a[3]), "r"(b[0]), "r"(b[1]));
}

// ======= weight convert: W [K,N] fp32 -> hi/lo [N,K] bf16 (transpose) =======
__global__ __launch_bounds__(256) void convert_w_k(
    const float* __restrict__ W, __nv_bfloat16* __restrict__ out, int Kd, int Nd)
{
    __shared__ float t[32][33];
    const int l = blockIdx.z;
    const float* Wl = W + (size_t)l * Kd * Nd;
    __nv_bfloat16* hi = out + (size_t)l * 2 * Kd * Nd;
    __nv_bfloat16* lo = hi + (size_t)Kd * Nd;
    const int nb = blockIdx.x * 32, kb = blockIdx.y * 32;
    const int tx = threadIdx.x & 31, ty = threadIdx.x >> 5;
    #pragma unroll
    for (int j = 0; j < 32; j += 8)
        t[ty + j][tx] = Wl[(size_t)(kb + ty + j) * Nd + nb + tx];
    __syncthreads();
    #pragma unroll
    for (int j = 0; j < 32; j += 8) {
        const int n = nb + ty + j, k = kb + tx;
        float v = t[tx][ty + j];
        __nv_bfloat16 h, l2; split_bf16(v, h, l2);
        hi[(size_t)n * Kd + k] = h;
        lo[(size_t)n * Kd + k] = l2;
    }
}

// ===================== GEMM flags / args ====================================
#define F_BIAS 1
#define F_RES  2
#define F_RELU 4
#define F_QKVOUT 8
#define F_SPLITOUT 16

struct GemmArgs {
    const __nv_bfloat16 *Ahi, *Alo;
    const __nv_bfloat16 *Bhi[3], *Blo[3];
    const float* bias[3];
    const float* Res;
    float* C[3];
    __nv_bfloat16 *Chi[3], *Clo[3];
    int K;
    int ldc;
};

// ===================== GEMM v4: BM=128 (kept for skinny GEMMs) ==============
#define PITB 80
#define AH_OFF 0
#define AL_OFF (128*PITB)
#define BH_OFF (2*128*PITB)
#define BL_OFF (3*128*PITB)
#define STGB   (4*128*PITB)
#define SMEM_GM (3*STGB)               // 122880

template<int FLAGS>
__global__ __launch_bounds__(256) void mma_gemm_k(GemmArgs ga)
{
    constexpr int BM = 128, BN = 128, BK = 32;
    extern __shared__ __nv_bfloat16 smb[];
    char* smc = (char*)smb;

    const int tid = threadIdx.x, wid = tid >> 5, lane = tid & 31;
    const int z = blockIdx.z;
    const int Kd = ga.K;
    const __nv_bfloat16* Ah = ga.Ahi + (size_t)blockIdx.y * BM * Kd;
    const __nv_bfloat16* Al = ga.Alo + (size_t)blockIdx.y * BM * Kd;
    const __nv_bfloat16* Bh = ga.Bhi[z] + (size_t)blockIdx.x * BN * Kd;
    const __nv_bfloat16* Bl = ga.Blo[z] + (size_t)blockIdx.x * BN * Kd;
    const int wm = wid & 3, wn = wid >> 2;

    auto stage_load = [&](int buf, int k0) {
        char* s = smc + buf * STGB;
        #pragma unroll
        for (int ss = 0; ss < 2; ss++) {
            const int slot = tid + ss * 256;
            const int r = slot >> 2, c = slot & 3;
            cpa16(s + AH_OFF + r * PITB + c * 16, Ah + (size_t)r * Kd + k0 + c * 8);
            cpa16(s + AL_OFF + r * PITB + c * 16, Al + (size_t)r * Kd + k0 + c * 8);
        }
        #pragma unroll
        for (int ss = 0; ss < 2; ss++) {
            const int slot = tid + ss * 256;
            const int r = slot >> 2, c = slot & 3;
            cpa16(s + BH_OFF + r * PITB + c * 16, Bh + (size_t)r * Kd + k0 + c * 8);
            cpa16(s + BL_OFF + r * PITB + c * 16, Bl + (size_t)r * Kd + k0 + c * 8);
        }
        CP_COMMIT();
    };

    uint32_t offA[2];
    #pragma unroll
    for (int ii = 0; ii < 2; ii++)
        offA[ii] = (uint32_t)((wm * 32 + ii * 16 + (lane & 15)) * PITB + ((lane >> 4) & 1) * 16);
    uint32_t offB[4];
    #pragma unroll
    for (int jj = 0; jj < 4; jj++)
        offB[jj] = (uint32_t)((wn * 64 + jj * 16 + (lane & 7) + ((lane >> 4) & 1) * 8) * PITB
                              + ((lane >> 3) & 1) * 16);

    const uint32_t smem_u32 = (uint32_t)__cvta_generic_to_shared(smc);

    float acc[2][8][4];
    #pragma unroll
    for (int i = 0; i < 2; i++)
        #pragma unroll
        for (int j = 0; j < 8; j++)
            #pragma unroll
            for (int e = 0; e < 4; e++) acc[i][j][e] = 0.f;

    const int nst = Kd / BK;
    stage_load(0, 0);
    stage_load(1, BK);
    for (int i = 0; i < nst; i++) {
        if (i + 1 < nst) { CP_WAIT1(); } else { CP_WAIT0(); }
        __syncthreads();
        if (i + 2 < nst) stage_load((i + 2) % 3, (i + 2) * BK);
        const uint32_t sb = smem_u32 + (uint32_t)((i % 3) * STGB);
        #pragma unroll
        for (int kk = 0; kk < BK; kk += 16) {
            const uint32_t kb = sb + kk * 2;
            uint32_t ah[2][4], al[2][4], bh[16], bl[16];
            #pragma unroll
            for (int ii = 0; ii < 2; ii++) {
                ldsm4(kb + AH_OFF + offA[ii], ah[ii]);
                ldsm4(kb + AL_OFF + offA[ii], al[ii]);
            }
            #pragma unroll
            for (int jj = 0; jj < 4; jj++) {
                ldsm4(kb + BH_OFF + offB[jj], bh + jj * 4);
                ldsm4(kb + BL_OFF + offB[jj], bl + jj * 4);
            }
            #pragma unroll
            for (int ii = 0; ii < 2; ii++)
                #pragma unroll
                for (int j = 0; j < 8; j++) mma16816(acc[ii][j], ah[ii], bh + j * 2);
            #pragma unroll
            for (int ii = 0; ii < 2; ii++)
                #pragma unroll
                for (int j = 0; j < 8; j++) mma16816(acc[ii][j], ah[ii], bl + j * 2);
            #pragma unroll
            for (int ii = 0; ii < 2; ii++)
                #pragma unroll
                for (int j = 0; j < 8; j++) mma16816(acc[ii][j], al[ii], bh + j * 2);
        }
        __syncthreads();
    }

    constexpr int SP = BN + 4;
    float* st = (float*)smb;
    const int er = lane >> 2, ec = (lane & 3) * 2;
    #pragma unroll
    for (int ii = 0; ii < 2; ii++)
        #pragma unroll
        for (int j = 0; j < 8; j++) {
            const int r0 = wm * 32 + ii * 16 + er;
            const int c0 = wn * 64 + j * 8 + ec;
            st[r0 * SP + c0]       = acc[ii][j][0];
            st[r0 * SP + c0 + 1]   = acc[ii][j][1];
            st[(r0+8) * SP + c0]     = acc[ii][j][2];
            st[(r0+8) * SP + c0 + 1] = acc[ii][j][3];
        }
    __syncthreads();

    const float* bias = ga.bias[z] + (size_t)blockIdx.x * BN;
    #pragma unroll
    for (int jj = 0; jj < 16; jj++) {
        const int idx = tid + jj * 256;
        const int r = idx >> 5, c4 = (idx & 31) * 4;
        float4 v;
        v.x = st[r * SP + c4 + 0]; v.y = st[r * SP + c4 + 1];
        v.z = st[r * SP + c4 + 2]; v.w = st[r * SP + c4 + 3];
        if (FLAGS & F_BIAS) {
            float4 b4 = *(const float4*)(bias + c4);
            v.x += b4.x; v.y += b4.y; v.z += b4.z; v.w += b4.w;
        }
        if (FLAGS & F_RELU) {
            v.x = fmaxf(v.x, 0.f); v.y = fmaxf(v.y, 0.f);
            v.z = fmaxf(v.z, 0.f); v.w = fmaxf(v.w, 0.f);
        }
        if (FLAGS & F_QKVOUT) {
            const int token = blockIdx.y * BM + r;
            const int bb = token >> 10, ss = token & 1023;
            const int f = blockIdx.x * BN + c4;
            const int hh2 = f >> 6, dk = f & 63;
            const size_t base = (((size_t)bb * Hh + hh2) * Ssz + ss) * DKk + dk;
            __nv_bfloat16 h[4], l[4];
            split_bf16(v.x, h[0], l[0]); split_bf16(v.y, h[1], l[1]);
            split_bf16(v.z, h[2], l[2]); split_bf16(v.w, h[3], l[3]);
            *(uint2*)(ga.Chi[z] + base) = *(uint2*)h;
            *(uint2*)(ga.Clo[z] + base) = *(uint2*)l;
        } else if (FLAGS & F_SPLITOUT) {
            const size_t base = (size_t)(blockIdx.y * BM + r) * ga.ldc + blockIdx.x * BN + c4;
            __nv_bfloat16 h[4], l[4];
            split_bf16(v.x, h[0], l[0]); split_bf16(v.y, h[1], l[1]);
            split_bf16(v.z, h[2], l[2]); split_bf16(v.w, h[3], l[3]);
            *(uint2*)(ga.Chi[z] + base) = *(uint2*)h;
            *(uint2*)(ga.Clo[z] + base) = *(uint2*)l;
        } else {
            if (FLAGS & F_RES) {
                const float* R = ga.Res + (size_t)blockIdx.y * BM * ga.ldc + (size_t)blockIdx.x * BN;
                float4 r4 = *(const float4*)(R + (size_t)r * ga.ldc + c4);
                v.x += r4.x; v.y += r4.y; v.z += r4.z; v.w += r4.w;
            }
            float* C = ga.C[z] + (size_t)blockIdx.y * BM * ga.ldc + (size_t)blockIdx.x * BN;
            *(float4*)(C + (size_t)r * ga.ldc + c4) = v;
        }
    }
}

// ===================== GEMM v5: BM=256, warp tile 64x64 =====================
#define AH5_OFF 0
#define AL5_OFF (256*PITB)
#define BH5_OFF (2*256*PITB)
#define BL5_OFF (2*256*PITB + 128*PITB)
#define STGB5   (2*256*PITB + 2*128*PITB)    // 61440 bytes
#define SMEM_GM5 (3*STGB5)                   // 184320

template<int FLAGS>
__global__ __launch_bounds__(256) void mma_gemm256_k(GemmArgs ga)
{
    constexpr int BM = 256, BN = 128, BK = 32;
    extern __shared__ __nv_bfloat16 smb[];
    char* smc = (char*)smb;

    const int tid = threadIdx.x, wid = tid >> 5, lane = tid & 31;
    const int z = blockIdx.z;
    const int Kd = ga.K;
    const __nv_bfloat16* Ah = ga.Ahi + (size_t)blockIdx.y * BM * Kd;
    const __nv_bfloat16* Al = ga.Alo + (size_t)blockIdx.y * BM * Kd;
    const __nv_bfloat16* Bh = ga.Bhi[z] + (size_t)blockIdx.x * BN * Kd;
    const __nv_bfloat16* Bl = ga.Blo[z] + (size_t)blockIdx.x * BN * Kd;
    const int wm = wid & 3, wn = wid >> 2;       // warp tile 64 x 64

    auto stage_load = [&](int buf, int k0) {
        char* s = smc + buf * STGB5;
        #pragma unroll
        for (int ss = 0; ss < 4; ss++) {          // A: 1024 chunk slots
            const int slot = tid + ss * 256;
            const int r = slot >> 2, c = slot & 3;
            cpa16(s + AH5_OFF + r * PITB + c * 16, Ah + (size_t)r * Kd + k0 + c * 8);
            cpa16(s + AL5_OFF + r * PITB + c * 16, Al + (size_t)r * Kd + k0 + c * 8);
        }
        #pragma unroll
        for (int ss = 0; ss < 2; ss++) {          // B: 512 chunk slots
            const int slot = tid + ss * 256;
            const int r = slot >> 2, c = slot & 3;
            cpa16(s + BH5_OFF + r * PITB + c * 16, Bh + (size_t)r * Kd + k0 + c * 8);
            cpa16(s + BL5_OFF + r * PITB + c * 16, Bl + (size_t)r * Kd + k0 + c * 8);
        }
        CP_COMMIT();
    };

    uint32_t offA[4];
    #pragma unroll
    for (int mi = 0; mi < 4; mi++)
        offA[mi] = (uint32_t)((wm * 64 + mi * 16 + (lane & 15)) * PITB + ((lane >> 4) & 1) * 16);
    uint32_t offB[4];
    #pragma unroll
    for (int nj = 0; nj < 4; nj++)
        offB[nj] = (uint32_t)((wn * 64 + nj * 16 + (lane & 7) + ((lane >> 4) & 1) * 8) * PITB
                              + ((lane >> 3) & 1) * 16);

    const uint32_t smem_u32 = (uint32_t)__cvta_generic_to_shared(smc);

    float acc[4][8][4];
    #pragma unroll
    for (int i = 0; i < 4; i++)
        #pragma unroll
        for (int j = 0; j < 8; j++)
            #pragma unroll
            for (int e = 0; e < 4; e++) acc[i][j][e] = 0.f;

    const int nst = Kd / BK;
    stage_load(0, 0);
    stage_load(1, BK);
    for (int i = 0; i < nst; i++) {
        if (i + 1 < nst) { CP_WAIT1(); } else { CP_WAIT0(); }
        __syncthreads();
        if (i + 2 < nst) stage_load((i + 2) % 3, (i + 2) * BK);
        const uint32_t sb = smem_u32 + (uint32_t)((i % 3) * STGB5);
        #pragma unroll
        for (int kk = 0; kk < BK; kk += 16) {
            const uint32_t kb = sb + kk * 2;
            uint32_t ah[4][4], al[4][4], bb[16];
            #pragma unroll
            for (int mi = 0; mi < 4; mi++) {
                ldsm4(kb + AH5_OFF + offA[mi], ah[mi]);
                ldsm4(kb + AL5_OFF + offA[mi], al[mi]);
            }
            #pragma unroll
            for (int nj = 0; nj < 4; nj++) ldsm4(kb + BH5_OFF + offB[nj], bb + nj * 4);
            #pragma unroll
            for (int mi = 0; mi < 4; mi++)
                #pragma unroll
                for (int j = 0; j < 8; j++) mma16816(acc[mi][j], ah[mi], bb + j * 2);
            #pragma unroll
            for (int mi = 0; mi < 4; mi++)
                #pragma unroll
                for (int j = 0; j < 8; j++) mma16816(acc[mi][j], al[mi], bb + j * 2);
            #pragma unroll
            for (int nj = 0; nj < 4; nj++) ldsm4(kb + BL5_OFF + offB[nj], bb + nj * 4);
            #pragma unroll
            for (int mi = 0; mi < 4; mi++)
                #pragma unroll
                for (int j = 0; j < 8; j++) mma16816(acc[mi][j], ah[mi], bb + j * 2);
        }
        __syncthreads();
    }

    // epilogue: acc -> SMEM staging (256 x 132) -> writeout
    constexpr int SP = BN + 4;
    float* st = (float*)smb;
    const int er = lane >> 2, ec = (lane & 3) * 2;
    #pragma unroll
    for (int mi = 0; mi < 4; mi++)
        #pragma unroll
        for (int j = 0; j < 8; j++) {
            const int r0 = wm * 64 + mi * 16 + er;
            const int c0 = wn * 64 + j * 8 + ec;
            st[r0 * SP + c0]       = acc[mi][j][0];
            st[r0 * SP + c0 + 1]   = acc[mi][j][1];
            st[(r0+8) * SP + c0]     = acc[mi][j][2];
            st[(r0+8) * SP + c0 + 1] = acc[mi][j][3];
        }
    __syncthreads();

    const float* bias = ga.bias[z] + (size_t)blockIdx.x * BN;
    #pragma unroll
    for (int jj = 0; jj < 32; jj++) {
        const int idx = tid + jj * 256;
        const int r = idx >> 5, c4 = (idx & 31) * 4;
        float4 v;
        v.x = st[r * SP + c4 + 0]; v.y = st[r * SP + c4 + 1];
        v.z = st[r * SP + c4 + 2]; v.w = st[r * SP + c4 + 3];
        if (FLAGS & F_BIAS) {
            float4 b4 = *(const float4*)(bias + c4);
            v.x += b4.x; v.y += b4.y; v.z += b4.z; v.w += b4.w;
        }
        if (FLAGS & F_RELU) {
            v.x = fmaxf(v.x, 0.f); v.y = fmaxf(v.y, 0.f);
            v.z = fmaxf(v.z, 0.f); v.w = fmaxf(v.w, 0.f);
        }
        if (FLAGS & F_QKVOUT) {
            const int token = blockIdx.y * BM + r;
            const int bb2 = token >> 10, ss = token & 1023;
            const int f = blockIdx.x * BN + c4;
            const int hh2 = f >> 6, dk = f & 63;
            const size_t base = (((size_t)bb2 * Hh + hh2) * Ssz + ss) * DKk + dk;
            __nv_bfloat16 h[4], l[4];
            split_bf16(v.x, h[0], l[0]); split_bf16(v.y, h[1], l[1]);
            split_bf16(v.z, h[2], l[2]); split_bf16(v.w, h[3], l[3]);
            *(uint2*)(ga.Chi[z] + base) = *(uint2*)h;
            *(uint2*)(ga.Clo[z] + base) = *(uint2*)l;
        } else if (FLAGS & F_SPLITOUT) {
            const size_t base = (size_t)(blockIdx.y * BM + r) * ga.ldc + blockIdx.x * BN + c4;
            __nv_bfloat16 h[4], l[4];
            split_bf16(v.x, h[0], l[0]); split_bf16(v.y, h[1], l[1]);
            split_bf16(v.z, h[2], l[2]); split_bf16(v.w, h[3], l[3]);
            *(uint2*)(ga.Chi[z] + base) = *(uint2*)h;
            *(uint2*)(ga.Clo[z] + base) = *(uint2*)l;
        } else {
            if (FLAGS & F_RES) {
                const float* R = ga.Res + (size_t)blockIdx.y * BM * ga.ldc + (size_t)blockIdx.x * BN;
                float4 r4 = *(const float4*)(R + (size_t)r * ga.ldc + c4);
                v.x += r4.x; v.y += r4.y; v.z += r4.z; v.w += r4.w;
            }
            float* C = ga.C[z] + (size_t)blockIdx.y * BM * ga.ldc + (size_t)blockIdx.x * BN;
            *(float4*)(C + (size_t)r * ga.ldc + c4) = v;
        }
    }
}

// ===================== attention: scores via HMMA (wmma) ====================
#define APIT 72
#define SMEM_SCORE (4 * 128 * APIT * 2)

__global__ __launch_bounds__(256) void attn_scores_mma(
    const __nv_bfloat16* __restrict__ Qh, const __nv_bfloat16* __restrict__ Ql,
    const __nv_bfloat16* __restrict__ Kh, const __nv_bfloat16* __restrict__ Kl,
    float* __restrict__ Sc)
{
    const int bm = blockIdx.y, bn = blockIdx.x;
    if (bn > bm) return;
    const int bh = blockIdx.z;
    extern __shared__ char sm[];
    __nv_bfloat16* sQh = (__nv_bfloat16*)sm;
    __nv_bfloat16* sQl = sQh + 128 * APIT;
    __nv_bfloat16* sKh = sQl + 128 * APIT;
    __nv_bfloat16* sKl = sKh + 128 * APIT;

    const int tid = threadIdx.x, wid = tid >> 5;
    const size_t qoff = ((size_t)bh * Ssz + bm * 128) * DKk;
    const size_t koff = ((size_t)bh * Ssz + bn * 128) * DKk;
    #pragma unroll
    for (int s = 0; s < 4; s++) {
        const int slot = tid + s * 256;
        const int r = slot >> 3, c8 = slot & 7;
        *(uint4*)&sQh[r * APIT + c8 * 8] = *(const uint4*)(Qh + qoff + (size_t)r * DKk + c8 * 8);
        *(uint4*)&sQl[r * APIT + c8 * 8] = *(const uint4*)(Ql + qoff + (size_t)r * DKk + c8 * 8);
        *(uint4*)&sKh[r * APIT + c8 * 8] = *(const uint4*)(Kh + koff + (size_t)r * DKk + c8 * 8);
        *(uint4*)&sKl[r * APIT + c8 * 8] = *(const uint4*)(Kl + koff + (size_t)r * DKk + c8 * 8);
    }
    __syncthreads();

    const int wm = wid & 3, wn = wid >> 2;
    wmma::fragment<wmma::accumulator, 16, 16, 16, float> acc[2][4];
    #pragma unroll
    for (int i = 0; i < 2; i++)
        #pragma unroll
        for (int j = 0; j < 4; j++) wmma::fill_fragment(acc[i][j], 0.0f);

    #pragma unroll
    for (int kk = 0; kk < 64; kk += 16) {
        wmma::fragment<wmma::matrix_a, 16, 16, 16, __nv_bfloat16, wmma::row_major> fah[2], fal[2];
        wmma::fragment<wmma::matrix_b, 16, 16, 16, __nv_bfloat16, wmma::col_major> fbh[4], fbl[4];
        #pragma unroll
        for (int ii = 0; ii < 2; ii++) {
            wmma::load_matrix_sync(fah[ii], sQh + (wm * 32 + ii * 16) * APIT + kk, APIT);
            wmma::load_matrix_sync(fal[ii], sQl + (wm * 32 + ii * 16) * APIT + kk, APIT);
        }
        #pragma unroll
        for (int j = 0; j < 4; j++) {
            wmma::load_matrix_sync(fbh[j], sKh + (wn * 64 + j * 16) * APIT + kk, APIT);
            wmma::load_matrix_sync(fbl[j], sKl + (wn * 64 + j * 16) * APIT + kk, APIT);
        }
        #pragma unroll
        for (int ii = 0; ii < 2; ii++)
            #pragma unroll
            for (int j = 0; j < 4; j++) {
                wmma::mma_sync(acc[ii][j], fah[ii], fbh[j], acc[ii][j]);
                wmma::mma_sync(acc[ii][j], fah[ii], fbl[j], acc[ii][j]);
                wmma::mma_sync(acc[ii][j], fal[ii], fbh[j], acc[ii][j]);
            }
    }
    float* Cb = Sc + (size_t)bh * Ssz * Ssz + (size_t)(bm * 128) * Ssz + bn * 128;
    #pragma unroll
    for (int ii = 0; ii < 2; ii++)
        #pragma unroll
        for (int j = 0; j < 4; j++) {
            #pragma unroll
            for (int t = 0; t < acc[ii][j].num_elements; t++) acc[ii][j].x[t] *= 0.125f;
            wmma::store_matrix_sync(Cb + (size_t)(wm * 32 + ii * 16) * Ssz + wn * 64 + j * 16,
                                    acc[ii][j], Ssz, wmma::mem_row_major);
        }
}

// ===================== softmax: fp32 in -> bf16 hi/lo probs =================
__global__ __launch_bounds__(256) void softmax_k(
    const float* __restrict__ Sc, __nv_bfloat16* __restrict__ Ph,
    __nv_bfloat16* __restrict__ Pl)
{
    const int warp = threadIdx.x >> 5, lane = threadIdx.x & 31;
    const int row = blockIdx.x * 8 + warp;
    const int bh = row >> 10, q = row & 1023;
    const float* r = Sc + (size_t)bh * Ssz * Ssz + (size_t)q * Ssz;
    const int n = q + 1;
    float vals[32];
    float m = -3.0e38f;
    #pragma unroll
    for (int i = 0; i < 32; i++) {
        const int k = lane + i * 32;
        float v = (k < n) ? r[k] : -3.0e38f;
        vals[i] = v; m = fmaxf(m, v);
    }
    #pragma unroll
    for (int off = 16; off; off >>= 1) m = fmaxf(m, __shfl_xor_sync(0xffffffffu, m, off));
    float s = 0.f;
    #pragma unroll
    for (int i = 0; i < 32; i++) { float e = __expf(vals[i] - m); vals[i] = e; s += e; }
    #pragma unroll
    for (int off = 16; off; off >>= 1) s += __shfl_xor_sync(0xffffffffu, s, off);
    const float inv = 1.0f / s;
    const int kend = ((q >> 7) + 1) << 7;
    __nv_bfloat16* ph = Ph + (size_t)bh * Ssz * Ssz + (size_t)q * Ssz;
    __nv_bfloat16* pl = Pl + (size_t)bh * Ssz * Ssz + (size_t)q * Ssz;
    #pragma unroll
    for (int i = 0; i < 32; i++) {
        const int k = lane + i * 32;
        if (k < kend) {
            float p = (k < n) ? vals[i] * inv : 0.f;
            __nv_bfloat16 h, l; split_bf16(p, h, l);
            ph[k] = h; pl[k] = l;
        }
    }
}

// ===================== O = P @ V via HMMA (split output) ====================
#define SMEM_AV ((128 * APIT * 2 + 64 * APIT * 2) * 2)

__global__ __launch_bounds__(256) void attn_av_mma(
    const __nv_bfloat16* __restrict__ Ph, const __nv_bfloat16* __restrict__ Pl,
    const __nv_bfloat16* __restrict__ Vh, const __nv_bfloat16* __restrict__ Vl,
    __nv_bfloat16* __restrict__ Oh, __nv_bfloat16* __restrict__ Ol)
{
    const int bh = blockIdx.z, bb = bh >> 4, hh = bh & 15;
    const int bm = blockIdx.x;
    extern __shared__ char sm[];
    __nv_bfloat16* sPh = (__nv_bfloat16*)sm;
    __nv_bfloat16* sPl = sPh + 128 * APIT;
    __nv_bfloat16* sVh = sPl + 128 * APIT;
    __nv_bfloat16* sVl = sVh + 64 * APIT;

    const int tid = threadIdx.x, wid = tid >> 5;
    const __nv_bfloat16* Pbh = Ph + (size_t)bh * Ssz * Ssz + (size_t)(bm * 128) * Ssz;
    const __nv_bfloat16* Pbl = Pl + (size_t)bh * Ssz * Ssz + (size_t)(bm * 128) * Ssz;
    const __nv_bfloat16* Vbh = Vh + (size_t)bh * Ssz * DKk;
    const __nv_bfloat16* Vbl = Vl + (size_t)bh * Ssz * DKk;

    wmma::fragment<wmma::accumulator, 16, 16, 16, float> acc[4];
    #pragma unroll
    for (int j = 0; j < 4; j++) wmma::fill_fragment(acc[j], 0.0f);

    const int Kmax = (bm + 1) * 128;
    for (int k0 = 0; k0 < Kmax; k0 += 64) {
        #pragma unroll
        for (int s = 0; s < 4; s++) {
            const int slot = tid + s * 256;
            const int r = slot >> 3, c8 = slot & 7;
            *(uint4*)&sPh[r * APIT + c8 * 8] = *(const uint4*)(Pbh + (size_t)r * Ssz + k0 + c8 * 8);
            *(uint4*)&sPl[r * APIT + c8 * 8] = *(const uint4*)(Pbl + (size_t)r * Ssz + k0 + c8 * 8);
        }
        #pragma unroll
        for (int s = 0; s < 2; s++) {
            const int slot = tid + s * 256;
            const int r = slot >> 3, c8 = slot & 7;
            *(uint4*)&sVh[r * APIT + c8 * 8] = *(const uint4*)(Vbh + (size_t)(k0 + r) * DKk + c8 * 8);
            *(uint4*)&sVl[r * APIT + c8 * 8] = *(const uint4*)(Vbl + (size_t)(k0 + r) * DKk + c8 * 8);
        }
        __syncthreads();
        #pragma unroll
        for (int kk = 0; kk < 64; kk += 16) {
            wmma::fragment<wmma::matrix_a, 16, 16, 16, __nv_bfloat16, wmma::row_major> fah, fal;
            wmma::fragment<wmma::matrix_b, 16, 16, 16, __nv_bfloat16, wmma::row_major> fbh[4], fbl[4];
            wmma::load_matrix_sync(fah, sPh + (wid * 16) * APIT + kk, APIT);
            wmma::load_matrix_sync(fal, sPl + (wid * 16) * APIT + kk, APIT);
            #pragma unroll
            for (int j = 0; j < 4; j++) {
                wmma::load_matrix_sync(fbh[j], sVh + kk * APIT + j * 16, APIT);
                wmma::load_matrix_sync(fbl[j], sVl + kk * APIT + j * 16, APIT);
            }
            #pragma unroll
            for (int j = 0; j < 4; j++) {
                wmma::mma_sync(acc[j], fah, fbh[j], acc[j]);
                wmma::mma_sync(acc[j], fah, fbl[j], acc[j]);
                wmma::mma_sync(acc[j], fal, fbh[j], acc[j]);
            }
        }
        __syncthreads();
    }
    float* stg = (float*)sm;
    #pragma unroll
    for (int j = 0; j < 4; j++)
        wmma::store_matrix_sync(stg + (wid * 16) * 68 + j * 16, acc[j], 68, wmma::mem_row_major);
    __syncthreads();
    #pragma unroll
    for (int s = 0; s < 8; s++) {
        const int slot = tid + s * 256;
        const int r = slot >> 4, c4 = (slot & 15) * 4;
        float4 v;
        v.x = stg[r * 68 + c4 + 0]; v.y = stg[r * 68 + c4 + 1];
        v.z = stg[r * 68 + c4 + 2]; v.w = stg[r * 68 + c4 + 3];
        __nv_bfloat16 h[4], l[4];
        split_bf16(v.x, h[0], l[0]); split_bf16(v.y, h[1], l[1]);
        split_bf16(v.z, h[2], l[2]); split_bf16(v.w, h[3], l[3]);
        const size_t base = ((size_t)bb * Ssz + bm * 128 + r) * Dm + hh * DKk + c4;
        *(uint2*)(Oh + base) = *(uint2*)h;
        *(uint2*)(Ol + base) = *(uint2*)l;
    }
}

// ===================== embedding / layernorm (split out) ====================
__global__ __launch_bounds__(256) void embed_k(
    const int* __restrict__ ids, const float* __restrict__ tok,
    const float* __restrict__ pos, float* __restrict__ x)
{
    const int row = blockIdx.x;
    const int s   = row & (Ssz - 1);
    const int id  = ids[row];
    const int t   = threadIdx.x;
    float4 tv = *(const float4*)(tok + (size_t)id * Dm + t * 4);
    float4 pv = *(const float4*)(pos + (size_t)s  * Dm + t * 4);
    float4 o; o.x = tv.x + pv.x; o.y = tv.y + pv.y; o.z = tv.z + pv.z; o.w = tv.w + pv.w;
    *(float4*)(x + (size_t)row * Dm + t * 4) = o;
}

__global__ __launch_bounds__(256) void layernorm_split_k(
    const float* __restrict__ x, const float* __restrict__ g,
    const float* __restrict__ be,
    __nv_bfloat16* __restrict__ oh, __nv_bfloat16* __restrict__ ol)
{
    const int row = blockIdx.x;
    const int t   = threadIdx.x;
    const float* xr = x + (size_t)row * Dm;
    float4 v = *(const float4*)(xr + t * 4);
    float s  = v.x + v.y + v.z + v.w;
    float ss = v.x*v.x + v.y*v.y + v.z*v.z + v.w*v.w;
    #pragma unroll
    for (int off = 16; off; off >>= 1) {
        s  += __shfl_xor_sync(0xffffffffu, s,  off);
        ss += __shfl_xor_sync(0xffffffffu, ss, off);
    }
    __shared__ float rs[8], rss[8];
    const int warp = t >> 5, lane = t & 31;
    if (lane == 0) { rs[warp] = s; rss[warp] = ss; }
    __syncthreads();
    s = 0.f; ss = 0.f;
    #pragma unroll
    for (int i = 0; i < 8; i++) { s += rs[i]; ss += rss[i]; }
    const float mean = s  * (1.0f / Dm);
    const float var  = ss * (1.0f / Dm) - mean * mean;
    const float rstd = rsqrtf(var + 1e-5f);
    float4 gv = *(const float4*)(g  + t * 4);
    float4 bv = *(const float4*)(be + t * 4);
    float o0 = (v.x - mean) * rstd * gv.x + bv.x;
    float o1 = (v.y - mean) * rstd * gv.y + bv.y;
    float o2 = (v.z - mean) * rstd * gv.z + bv.z;
    float o3 = (v.w - mean) * rstd * gv.w + bv.w;
    __nv_bfloat16 h[4], l[4];
    split_bf16(o0, h[0], l[0]); split_bf16(o1, h[1], l[1]);
    split_bf16(o2, h[2], l[2]); split_bf16(o3, h[3], l[3]);
    *(uint2*)(oh + (size_t)row * Dm + t * 4) = *(uint2*)h;
    *(uint2*)(ol + (size_t)row * Dm + t * 4) = *(uint2*)l;
}

// ===================== driver ===============================================
extern "C" void kernel_launch(void* const* d_in, const int* in_sizes, int n_in,
                              void* d_out, int out_size)
{
    const int*   ids  = (const int*)  d_in[0];
    const float* tok  = (const float*)d_in[1];
    const float* pos  = (const float*)d_in[2];
    const float* Wq   = (const float*)d_in[3];
    const float* bq   = (const float*)d_in[4];
    const float* Wk   = (const float*)d_in[5];
    const float* bk   = (const float*)d_in[6];
    const float* Wv   = (const float*)d_in[7];
    const float* bv   = (const float*)d_in[8];
    const float* Wo   = (const float*)d_in[9];
    const float* bo   = (const float*)d_in[10];
    const float* W1   = (const float*)d_in[11];
    const float* b1   = (const float*)d_in[12];
    const float* W2   = (const float*)d_in[13];
    const float* b2   = (const float*)d_in[14];
    const float* ln1g = (const float*)d_in[15];
    const float* ln1b = (const float*)d_in[16];
    const float* ln2g = (const float*)d_in[17];
    const float* ln2b = (const float*)d_in[18];
    const float* lnfg = (const float*)d_in[19];
    const float* lnfb = (const float*)d_in[20];
    const float* Wout = (const float*)d_in[21];
    const float* bout = (const float*)d_in[22];
    float* out = (float*)d_out;

    float *x, *sc;
    __nv_bfloat16 *wc, *hh, *hl, *oh, *ol, *ffh, *ffl;
    __nv_bfloat16 *qh, *ql, *kh, *kl, *vh, *vl, *ph, *pl;
    cudaGetSymbolAddress((void**)&x,  g_x);
    cudaGetSymbolAddress((void**)&sc, g_sc);
    cudaGetSymbolAddress((void**)&wc, g_wc);
    cudaGetSymbolAddress((void**)&hh, g_hh);   cudaGetSymbolAddress((void**)&hl, g_hl);
    cudaGetSymbolAddress((void**)&oh, g_oh);   cudaGetSymbolAddress((void**)&ol, g_ol);
    cudaGetSymbolAddress((void**)&ffh, g_ffh); cudaGetSymbolAddress((void**)&ffl, g_ffl);
    cudaGetSymbolAddress((void**)&qh, g_qh);   cudaGetSymbolAddress((void**)&ql, g_ql);
    cudaGetSymbolAddress((void**)&kh, g_kh);   cudaGetSymbolAddress((void**)&kl, g_kl);
    cudaGetSymbolAddress((void**)&vh, g_vh);   cudaGetSymbolAddress((void**)&vl, g_vl);
    cudaGetSymbolAddress((void**)&ph, g_ph);   cudaGetSymbolAddress((void**)&pl, g_pl);

    cudaFuncSetAttribute(mma_gemm_k<F_BIAS|F_RES>,                cudaFuncAttributeMaxDynamicSharedMemorySize, SMEM_GM);
    cudaFuncSetAttribute(mma_gemm256_k<F_BIAS>,                   cudaFuncAttributeMaxDynamicSharedMemorySize, SMEM_GM5);
    cudaFuncSetAttribute(mma_gemm256_k<F_BIAS|F_QKVOUT>,          cudaFuncAttributeMaxDynamicSharedMemorySize, SMEM_GM5);
    cudaFuncSetAttribute(mma_gemm256_k<F_BIAS|F_RELU|F_SPLITOUT>, cudaFuncAttributeMaxDynamicSharedMemorySize, SMEM_GM5);
    cudaFuncSetAttribute(attn_scores_mma, cudaFuncAttributeMaxDynamicSharedMemorySize, SMEM_SCORE);
    cudaFuncSetAttribute(attn_av_mma,     cudaFuncAttributeMaxDynamicSharedMemorySize, SMEM_AV);

    convert_w_k<<<dim3(Dm/32, Dm/32, Ll), 256>>>(Wq,   wc + OFF_Q,  Dm, Dm);
    convert_w_k<<<dim3(Dm/32, Dm/32, Ll), 256>>>(Wk,   wc + OFF_K,  Dm, Dm);
    convert_w_k<<<dim3(Dm/32, Dm/32, Ll), 256>>>(Wv,   wc + OFF_V,  Dm, Dm);
    convert_w_k<<<dim3(Dm/32, Dm/32, Ll), 256>>>(Wo,   wc + OFF_O,  Dm, Dm);
    convert_w_k<<<dim3(Ff/32, Dm/32, Ll), 256>>>(W1,   wc + OFF_W1, Dm, Ff);
    convert_w_k<<<dim3(Dm/32, Ff/32, Ll), 256>>>(W2,   wc + OFF_W2, Ff, Dm);
    convert_w_k<<<dim3(Vv/32, Dm/32, 1),  256>>>(Wout, wc + OFF_WO, Dm, Vv);

    embed_k<<<TOK, 256>>>(ids, tok, pos, x);

    const dim3 gQKV (Dm/128, TOK/256, 3);     // v5: 8 x 8 x 3 = 192 CTAs
    const dim3 gProj(Dm/128, TOK/128, 1);     // v4: 128 CTAs
    const dim3 gFfn1(Ff/128, TOK/256, 1);     // v5: 256 CTAs
    const dim3 gLogit(Vv/128, TOK/256, 1);    // v5: 2000 CTAs
    const dim3 gScore(Ssz/128, Ssz/128, BH);
    const dim3 gAv(Ssz/128, 1, BH);

    for (int l = 0; l < Ll; l++) {
        const size_t oDb = (size_t)l * Dm;
        const size_t oFb = (size_t)l * Ff;
        const size_t oq = (size_t)l * SQW, o1 = (size_t)l * SW1;

        layernorm_split_k<<<TOK, 256>>>(x, ln1g + oDb, ln1b + oDb, hh, hl);

        GemmArgs qa{};
        qa.Ahi = hh; qa.Alo = hl; qa.K = Dm; qa.ldc = Dm;
        qa.Bhi[0] = wc + OFF_Q + oq; qa.Blo[0] = qa.Bhi[0] + (size_t)Dm*Dm;
        qa.Bhi[1] = wc + OFF_K + oq; qa.Blo[1] = qa.Bhi[1] + (size_t)Dm*Dm;
        qa.Bhi[2] = wc + OFF_V + oq; qa.Blo[2] = qa.Bhi[2] + (size_t)Dm*Dm;
        qa.bias[0] = bq + oDb; qa.bias[1] = bk + oDb; qa.bias[2] = bv + oDb;
        qa.Chi[0] = qh; qa.Clo[0] = ql;
        qa.Chi[1] = kh; qa.Clo[1] = kl;
        qa.Chi[2] = vh; qa.Clo[2] = vl;
        mma_gemm256_k<F_BIAS|F_QKVOUT><<<gQKV, 256, SMEM_GM5>>>(qa);

        attn_scores_mma<<<gScore, 256, SMEM_SCORE>>>(qh, ql, kh, kl, sc);
        softmax_k<<<(BH*Ssz)/8, 256>>>(sc, ph, pl);
        attn_av_mma<<<gAv, 256, SMEM_AV>>>(ph, pl, vh, vl, oh, ol);

        GemmArgs oa{};
        oa.Ahi = oh; oa.Alo = ol; oa.K = Dm; oa.ldc = Dm;
        oa.Bhi[0] = wc + OFF_O + oq; oa.Blo[0] = oa.Bhi[0] + (size_t)Dm*Dm;
        oa.bias[0] = bo + oDb; oa.Res = x; oa.C[0] = x;
        mma_gemm_k<F_BIAS|F_RES><<<gProj, 256, SMEM_GM>>>(oa);

        layernorm_split_k<<<TOK, 256>>>(x, ln2g + oDb, ln2b + oDb, hh, hl);

        GemmArgs fa{};
        fa.Ahi = hh; fa.Alo = hl; fa.K = Dm; fa.ldc = Ff;
        fa.Bhi[0] = wc + OFF_W1 + o1; fa.Blo[0] = fa.Bhi[0] + (size_t)Dm*Ff;
        fa.bias[0] = b1 + oFb; fa.Chi[0] = ffh; fa.Clo[0] = ffl;
        mma_gemm256_k<F_BIAS|F_RELU|F_SPLITOUT><<<gFfn1, 256, SMEM_GM5>>>(fa);

        GemmArgs f2{};
        f2.Ahi = ffh; f2.Alo = ffl; f2.K = Ff; f2.ldc = Dm;
        f2.Bhi[0] = wc + OFF_W2 + o1; f2.Blo[0] = f2.Bhi[0] + (size_t)Dm*Ff;
        f2.bias[0] = b2 + oDb; f2.Res = x; f2.C[0] = x;
        mma_gemm_k<F_BIAS|F_RES><<<gProj, 256, SMEM_GM>>>(f2);
    }

    layernorm_split_k<<<TOK, 256>>>(x, lnfg, lnfb, hh, hl);

    GemmArgs la{};
    la.Ahi = hh; la.Alo = hl; la.K = Dm; la.ldc = Vv;
    la.Bhi[0] = wc + OFF_WO; la.Blo[0] = la.Bhi[0] + (size_t)Dm*Vv;
    la.bias[0] = bout; la.C[0] = out;
    mma_gemm256_k<F_BIAS><<<gLogit, 256, SMEM_GM5>>>(la);
}